// round 1
// baseline (speedup 1.0000x reference)
#include <cuda_runtime.h>
#include <cuda_bf16.h>
#include <math.h>

#define D_MODEL 1024
#define N_HEADS 16
#define D_K 64
#define D_FF 4096
#define N_LAYERS 6
#define BATCH 4
#define SEQ 1024
#define ROWS (BATCH * SEQ)   // 4096

// ---------------- scratch (device globals; no allocation allowed) ----------
__device__ float g_x[ROWS * D_MODEL];
__device__ float g_q[ROWS * D_MODEL];
__device__ float g_k[ROWS * D_MODEL];
__device__ float g_v[ROWS * D_MODEL];
__device__ float g_a[ROWS * D_MODEL];
__device__ float g_t[ROWS * D_MODEL];
__device__ float g_h[ROWS * D_FF];

// ---------------- embedding + positional encoding ---------------------------
__global__ void embed_kernel(const int* __restrict__ src,
                             const float* __restrict__ emb,
                             const float* __restrict__ pe,
                             float* __restrict__ x) {
    int row = blockIdx.x;              // b*SEQ + s
    int s = row & (SEQ - 1);
    int tok = src[row];
    const float* erow = emb + (size_t)tok * D_MODEL;
    const float* prow = pe + (size_t)s * D_MODEL;
    float* xrow = x + (size_t)row * D_MODEL;
    for (int d = threadIdx.x; d < D_MODEL; d += blockDim.x)
        xrow[d] = erow[d] * 32.0f + prow[d];   // sqrt(1024) = 32
}

// ---------------- SGEMM: C[M,N] = A[M,K] @ B[K,N] + bias (+relu) -----------
// 64x64 tile, BK=16, 256 threads, 4x4 micro-tile per thread.
__global__ __launch_bounds__(256)
void gemm_bias_kernel(const float* __restrict__ A,
                      const float* __restrict__ B,
                      const float* __restrict__ bias,
                      float* __restrict__ C,
                      int M, int N, int K, int relu) {
    __shared__ float As[16][68];   // transposed A tile, padded (conflict-free STS)
    __shared__ float Bs[16][64];

    const int tid = threadIdx.x;
    const int tr = tid >> 4;       // 0..15  (row group in compute)
    const int tc = tid & 15;       // 0..15  (col group in compute)

    const int ar = tid >> 2;            // 0..63 : A-tile row loaded
    const int ak = (tid & 3) << 2;      // 0,4,8,12 : A-tile k offset (float4)
    const int br = tid >> 4;            // 0..15 : B-tile k row loaded
    const int bc = (tid & 15) << 2;     // 0..60 : B-tile col offset (float4)

    const int row_base = blockIdx.y * 64;
    const int col_base = blockIdx.x * 64;

    const float* Aptr = A + (size_t)(row_base + ar) * K + ak;
    const float* Bptr = B + (size_t)br * N + col_base + bc;

    float acc[4][4];
#pragma unroll
    for (int i = 0; i < 4; i++)
#pragma unroll
        for (int j = 0; j < 4; j++) acc[i][j] = 0.0f;

    for (int k0 = 0; k0 < K; k0 += 16) {
        float4 a4 = *(const float4*)(Aptr + k0);
        float4 b4 = *(const float4*)(Bptr + (size_t)k0 * N);
        As[ak + 0][ar] = a4.x;
        As[ak + 1][ar] = a4.y;
        As[ak + 2][ar] = a4.z;
        As[ak + 3][ar] = a4.w;
        *(float4*)&Bs[br][bc] = b4;
        __syncthreads();

#pragma unroll
        for (int kk = 0; kk < 16; kk++) {
            float4 av = *(const float4*)&As[kk][tr << 2];
            float4 bv = *(const float4*)&Bs[kk][tc << 2];
            float aj[4] = {av.x, av.y, av.z, av.w};
            float bj[4] = {bv.x, bv.y, bv.z, bv.w};
#pragma unroll
            for (int i = 0; i < 4; i++)
#pragma unroll
                for (int j = 0; j < 4; j++)
                    acc[i][j] = fmaf(aj[i], bj[j], acc[i][j]);
        }
        __syncthreads();
    }

    const int row0 = row_base + (tr << 2);
    const int col0 = col_base + (tc << 2);
    float4 bb = *(const float4*)(bias + col0);
#pragma unroll
    for (int i = 0; i < 4; i++) {
        float4 v;
        v.x = acc[i][0] + bb.x;
        v.y = acc[i][1] + bb.y;
        v.z = acc[i][2] + bb.z;
        v.w = acc[i][3] + bb.w;
        if (relu) {
            v.x = fmaxf(v.x, 0.0f); v.y = fmaxf(v.y, 0.0f);
            v.z = fmaxf(v.z, 0.0f); v.w = fmaxf(v.w, 0.0f);
        }
        *(float4*)(C + (size_t)(row0 + i) * N + col0) = v;
    }
}

// ---------------- fused attention: one block per (b,h,q) --------------------
__global__ __launch_bounds__(128)
void attn_kernel(const float* __restrict__ Q,
                 const float* __restrict__ K,
                 const float* __restrict__ V,
                 const int* __restrict__ mask,
                 float* __restrict__ O) {
    const int q = blockIdx.x;
    const int h = blockIdx.y;
    const int b = blockIdx.z;
    const int tid = threadIdx.x;   // 128 threads

    __shared__ float qv[D_K];
    __shared__ float sc[SEQ];
    __shared__ float red[128];

    const float* qrow = Q + ((size_t)(b * SEQ + q)) * D_MODEL + h * D_K;
    if (tid < D_K) qv[tid] = qrow[tid];
    __syncthreads();

    const int* mrow = mask + (size_t)b * SEQ;   // mask shape (B,1,1,S)

    float lmax = -1e30f;
    for (int k = tid; k < SEQ; k += 128) {
        const float* krow = K + ((size_t)(b * SEQ + k)) * D_MODEL + h * D_K;
        float s = 0.0f;
#pragma unroll
        for (int d = 0; d < D_K; d += 4) {
            float4 kv = *(const float4*)(krow + d);
            s = fmaf(qv[d], kv.x, s);
            s = fmaf(qv[d + 1], kv.y, s);
            s = fmaf(qv[d + 2], kv.z, s);
            s = fmaf(qv[d + 3], kv.w, s);
        }
        s *= 0.125f;                       // D_K^-0.5
        if (mrow[k] == 0) s = -1e9f;
        sc[k] = s;
        lmax = fmaxf(lmax, s);
    }
    red[tid] = lmax;
    __syncthreads();
    for (int off = 64; off > 0; off >>= 1) {
        if (tid < off) red[tid] = fmaxf(red[tid], red[tid + off]);
        __syncthreads();
    }
    float m = red[0];
    __syncthreads();

    float lsum = 0.0f;
    for (int k = tid; k < SEQ; k += 128) {
        float e = __expf(sc[k] - m);
        sc[k] = e;
        lsum += e;
    }
    red[tid] = lsum;
    __syncthreads();
    for (int off = 64; off > 0; off >>= 1) {
        if (tid < off) red[tid] += red[tid + off];
        __syncthreads();
    }
    float inv = 1.0f / red[0];
    __syncthreads();

    // AV: 128 threads = 2 k-halves x 64 dims
    const int d = tid & 63;
    const int half = tid >> 6;
    float accv = 0.0f;
    const float* Vb = V + ((size_t)(b * SEQ)) * D_MODEL + h * D_K + d;
    for (int k = half * 512; k < half * 512 + 512; k++)
        accv = fmaf(sc[k], Vb[(size_t)k * D_MODEL], accv);
    red[tid] = accv;
    __syncthreads();
    if (half == 0)
        O[((size_t)(b * SEQ + q)) * D_MODEL + h * D_K + d] =
            (red[tid] + red[tid + 64]) * inv;
}

// ---------------- fused residual add + LayerNorm (in-place safe) -----------
__global__ __launch_bounds__(256)
void add_ln_kernel(const float* __restrict__ x,
                   const float* __restrict__ r,
                   const float* __restrict__ g,
                   const float* __restrict__ bta,
                   float* __restrict__ y) {
    const int row = blockIdx.x;
    const int tid = threadIdx.x;   // 256, D=1024 -> 4 per thread
    const float* xr = x + (size_t)row * D_MODEL;
    const float* rr = r + (size_t)row * D_MODEL;
    float* yr = y + (size_t)row * D_MODEL;

    float vals[4];
    float s = 0.0f, ss = 0.0f;
#pragma unroll
    for (int i = 0; i < 4; i++) {
        int c = tid + 256 * i;
        float v = xr[c] + rr[c];
        vals[i] = v;
        s += v;
        ss = fmaf(v, v, ss);
    }
    __shared__ float rs[256], rss[256];
    rs[tid] = s; rss[tid] = ss;
    __syncthreads();
    for (int off = 128; off > 0; off >>= 1) {
        if (tid < off) { rs[tid] += rs[tid + off]; rss[tid] += rss[tid + off]; }
        __syncthreads();
    }
    float mean = rs[0] * (1.0f / D_MODEL);
    float var = rss[0] * (1.0f / D_MODEL) - mean * mean;
    float inv = rsqrtf(var + 1e-5f);
#pragma unroll
    for (int i = 0; i < 4; i++) {
        int c = tid + 256 * i;
        yr[c] = (vals[i] - mean) * inv * g[c] + bta[c];
    }
}

// ---------------- host orchestration ---------------------------------------
extern "C" void kernel_launch(void* const* d_in, const int* in_sizes, int n_in,
                              void* d_out, int out_size) {
    const int*   src  = (const int*)d_in[0];
    const int*   mask = (const int*)d_in[1];
    const float* emb  = (const float*)d_in[2];
    const float* pe   = (const float*)d_in[3];
    const float* wq = (const float*)d_in[4];
    const float* bq = (const float*)d_in[5];
    const float* wk = (const float*)d_in[6];
    const float* bk = (const float*)d_in[7];
    const float* wv = (const float*)d_in[8];
    const float* bv = (const float*)d_in[9];
    const float* wo = (const float*)d_in[10];
    const float* bo = (const float*)d_in[11];
    const float* w1 = (const float*)d_in[12];
    const float* b1 = (const float*)d_in[13];
    const float* w2 = (const float*)d_in[14];
    const float* b2 = (const float*)d_in[15];
    const float* g1  = (const float*)d_in[16];
    const float* be1 = (const float*)d_in[17];
    const float* g2  = (const float*)d_in[18];
    const float* be2 = (const float*)d_in[19];
    float* out = (float*)d_out;

    float *px, *pq, *pk, *pv, *pa, *pt, *ph;
    cudaGetSymbolAddress((void**)&px, g_x);
    cudaGetSymbolAddress((void**)&pq, g_q);
    cudaGetSymbolAddress((void**)&pk, g_k);
    cudaGetSymbolAddress((void**)&pv, g_v);
    cudaGetSymbolAddress((void**)&pa, g_a);
    cudaGetSymbolAddress((void**)&pt, g_t);
    cudaGetSymbolAddress((void**)&ph, g_h);

    embed_kernel<<<ROWS, 256>>>(src, emb, pe, px);

    dim3 gemm_dd(D_MODEL / 64, ROWS / 64);   // [4096,1024,*]
    dim3 gemm_df(D_FF / 64,    ROWS / 64);   // [4096,4096,1024]
    dim3 attn_grid(SEQ, N_HEADS, BATCH);

    for (int l = 0; l < N_LAYERS; l++) {
        size_t wofs  = (size_t)l * D_MODEL * D_MODEL;
        size_t bofs  = (size_t)l * D_MODEL;
        size_t w1ofs = (size_t)l * D_MODEL * D_FF;
        size_t b1ofs = (size_t)l * D_FF;
        size_t w2ofs = (size_t)l * D_FF * D_MODEL;

        gemm_bias_kernel<<<gemm_dd, 256>>>(px, wq + wofs, bq + bofs, pq,
                                           ROWS, D_MODEL, D_MODEL, 0);
        gemm_bias_kernel<<<gemm_dd, 256>>>(px, wk + wofs, bk + bofs, pk,
                                           ROWS, D_MODEL, D_MODEL, 0);
        gemm_bias_kernel<<<gemm_dd, 256>>>(px, wv + wofs, bv + bofs, pv,
                                           ROWS, D_MODEL, D_MODEL, 0);

        attn_kernel<<<attn_grid, 128>>>(pq, pk, pv, mask, pa);

        gemm_bias_kernel<<<gemm_dd, 256>>>(pa, wo + wofs, bo + bofs, pt,
                                           ROWS, D_MODEL, D_MODEL, 0);
        add_ln_kernel<<<ROWS, 256>>>(px, pt, g1 + bofs, be1 + bofs, px);

        gemm_bias_kernel<<<gemm_df, 256>>>(px, w1 + w1ofs, b1 + b1ofs, ph,
                                           ROWS, D_FF, D_MODEL, 1);
        gemm_bias_kernel<<<gemm_dd, 256>>>(ph, w2 + w2ofs, b2 + bofs, pt,
                                           ROWS, D_MODEL, D_FF, 0);
        add_ln_kernel<<<ROWS, 256>>>(px, pt, g2 + bofs, be2 + bofs, px);
    }

    cudaMemcpyAsync(out, px, (size_t)ROWS * D_MODEL * sizeof(float),
                    cudaMemcpyDeviceToDevice);
}

// round 5
// speedup vs baseline: 1.2484x; 1.2484x over previous
#include <cuda_runtime.h>
#include <cuda_bf16.h>
#include <math.h>
#include <stdint.h>

#define D_MODEL 1024
#define N_HEADS 16
#define D_K 64
#define D_FF 4096
#define N_LAYERS 6
#define BATCH 4
#define SEQ 1024
#define ROWS (BATCH * SEQ)   // 4096

// ---------------- scratch (device globals; no allocation allowed) ----------
__device__ float g_x[ROWS * D_MODEL];
__device__ float g_q[ROWS * D_MODEL];
__device__ float g_k[ROWS * D_MODEL];
__device__ float g_v[ROWS * D_MODEL];
__device__ float g_a[ROWS * D_MODEL];
__device__ float g_t[ROWS * D_MODEL];
__device__ float g_h[ROWS * D_FF];

// activation split buffers (max K = 4096)
__device__ __nv_bfloat16 g_ah[(size_t)ROWS * D_FF];
__device__ __nv_bfloat16 g_al[(size_t)ROWS * D_FF];

// transposed + split weights: [N,K] K-major bf16, hi and lo parts
__device__ __nv_bfloat16 g_wqt_h[6u*1024*1024], g_wqt_l[6u*1024*1024];
__device__ __nv_bfloat16 g_wkt_h[6u*1024*1024], g_wkt_l[6u*1024*1024];
__device__ __nv_bfloat16 g_wvt_h[6u*1024*1024], g_wvt_l[6u*1024*1024];
__device__ __nv_bfloat16 g_wot_h[6u*1024*1024], g_wot_l[6u*1024*1024];
__device__ __nv_bfloat16 g_w1t_h[6u*4096*1024], g_w1t_l[6u*4096*1024];
__device__ __nv_bfloat16 g_w2t_h[6u*4096*1024], g_w2t_l[6u*4096*1024];

// ---------------- PTX helpers ------------------------------------------------
__device__ __forceinline__ uint32_t smem_u32(const void* p) {
    uint32_t a;
    asm("{ .reg .u64 t; cvta.to.shared.u64 t, %1; cvt.u32.u64 %0, t; }"
        : "=r"(a) : "l"(p));
    return a;
}

__device__ __forceinline__ void cp16(uint32_t s, const void* g) {
    asm volatile("cp.async.cg.shared.global [%0], [%1], 16;"
                 :: "r"(s), "l"(g) : "memory");
}

__device__ __forceinline__ void ldsm4(uint32_t* r, uint32_t addr) {
    asm volatile("ldmatrix.sync.aligned.m8n8.x4.shared.b16 {%0,%1,%2,%3}, [%4];"
                 : "=r"(r[0]), "=r"(r[1]), "=r"(r[2]), "=r"(r[3]) : "r"(addr));
}

__device__ __forceinline__ void mma16816(float* c, const uint32_t* a,
                                         const uint32_t* b) {
    asm volatile(
        "mma.sync.aligned.m16n8k16.row.col.f32.bf16.bf16.f32 "
        "{%0,%1,%2,%3}, {%4,%5,%6,%7}, {%8,%9}, {%0,%1,%2,%3};"
        : "+f"(c[0]), "+f"(c[1]), "+f"(c[2]), "+f"(c[3])
        : "r"(a[0]), "r"(a[1]), "r"(a[2]), "r"(a[3]), "r"(b[0]), "r"(b[1]));
}

// ---------------- weight transpose + bf16 hi/lo split -----------------------
__global__ void transpose_split_kernel(const float* __restrict__ W,
                                       __nv_bfloat16* __restrict__ Th,
                                       __nv_bfloat16* __restrict__ Tl,
                                       int K, int N) {
    __shared__ float t[32][33];
    size_t lofs = (size_t)blockIdx.z * K * N;
    const float* Wl = W + lofs;
    int n0 = blockIdx.x * 32, k0 = blockIdx.y * 32;
    int tx = threadIdx.x, ty = threadIdx.y;
#pragma unroll
    for (int i = ty; i < 32; i += 8)
        t[i][tx] = Wl[(size_t)(k0 + i) * N + n0 + tx];
    __syncthreads();
#pragma unroll
    for (int i = ty; i < 32; i += 8) {
        float v = t[tx][i];
        __nv_bfloat16 h = __float2bfloat16(v);
        float lo = v - __bfloat162float(h);
        size_t o = lofs + (size_t)(n0 + i) * K + k0 + tx;
        Th[o] = h;
        Tl[o] = __float2bfloat16(lo);
    }
}

// ---------------- activation split: fp32 -> bf16 hi/lo ----------------------
__global__ __launch_bounds__(256)
void split_a_kernel(const float* __restrict__ X,
                    __nv_bfloat16* __restrict__ H,
                    __nv_bfloat16* __restrict__ L, int n4) {
    int i = blockIdx.x * 256 + threadIdx.x;
    if (i >= n4) return;
    float4 v = ((const float4*)X)[i];
    __nv_bfloat162 h0 = __floats2bfloat162_rn(v.x, v.y);
    __nv_bfloat162 h1 = __floats2bfloat162_rn(v.z, v.w);
    float2 f0 = __bfloat1622float2(h0);
    float2 f1 = __bfloat1622float2(h1);
    __nv_bfloat162 l0 = __floats2bfloat162_rn(v.x - f0.x, v.y - f0.y);
    __nv_bfloat162 l1 = __floats2bfloat162_rn(v.z - f1.x, v.w - f1.y);
    ((__nv_bfloat162*)H)[2 * i] = h0;
    ((__nv_bfloat162*)H)[2 * i + 1] = h1;
    ((__nv_bfloat162*)L)[2 * i] = l0;
    ((__nv_bfloat162*)L)[2 * i + 1] = l1;
}

// ---------------- mma.sync bf16 split-3 GEMM --------------------------------
// C[M,N] = A[M,K] @ B[N,K]^T + bias, A/B given as bf16 hi/lo pairs.
// 128x128 tile, BK=32, 256 threads, warp grid 4(M) x 2(N), warp tile 32x64.
#define S_AH 0
#define S_AL 10240
#define S_BH 20480
#define S_BL 30720
#define S_BUF 40960
#define GEMM_SMEM_BYTES (2 * S_BUF)   // 81920

__global__ __launch_bounds__(256, 1)
void gemm_tc(const __nv_bfloat16* __restrict__ Ah,
             const __nv_bfloat16* __restrict__ Al,
             const __nv_bfloat16* __restrict__ Bh,
             const __nv_bfloat16* __restrict__ Bl,
             const float* __restrict__ bias,
             float* __restrict__ C,
             int M, int N, int K, int relu) {
    extern __shared__ char sm[];
    const uint32_t sb = smem_u32(sm);

    const int tid = threadIdx.x;
    const int l = tid & 31, w = tid >> 5;
    const int wm = w & 3, wn = w >> 2;
    const int m0 = blockIdx.y * 128, n0 = blockIdx.x * 128;

    // loader mapping: thread -> row (0..127), two adjacent 16B chunks
    const int lr = tid >> 1;
    const int lkc = (tid & 1) * 2;   // chunk index 0 or 2 (of 4 per row)

    const __nv_bfloat16* agh = Ah + (size_t)(m0 + lr) * K + lkc * 8;
    const __nv_bfloat16* agl = Al + (size_t)(m0 + lr) * K + lkc * 8;
    const __nv_bfloat16* bgh = Bh + (size_t)(n0 + lr) * K + lkc * 8;
    const __nv_bfloat16* bgl = Bl + (size_t)(n0 + lr) * K + lkc * 8;
    const uint32_t srow = lr * 80 + lkc * 16;

    auto issue = [&](int c, int b) {
        const uint32_t o = sb + b * S_BUF + srow;
        const size_t go = (size_t)c * 32;
        cp16(o + S_AH,      agh + go);
        cp16(o + S_AH + 16, agh + go + 8);
        cp16(o + S_AL,      agl + go);
        cp16(o + S_AL + 16, agl + go + 8);
        cp16(o + S_BH,      bgh + go);
        cp16(o + S_BH + 16, bgh + go + 8);
        cp16(o + S_BL,      bgl + go);
        cp16(o + S_BL + 16, bgl + go + 8);
        asm volatile("cp.async.commit_group;" ::: "memory");
    };

    float acc[2][8][4] = {};

    const int NCk = K >> 5;
    issue(0, 0);

    // precomputed ldmatrix lane addressing
    const int a_row = wm * 32 + (l & 15);
    const int a_kb = ((l >> 4) << 3) * 2;            // +0 or +16 bytes
    const int b_n = wn * 64 + ((l >> 4) << 3) + (l & 7);
    const int b_kb = (((l >> 3) & 1) << 3) * 2;

    for (int c = 0; c < NCk; c++) {
        if (c + 1 < NCk) {
            issue(c + 1, (c + 1) & 1);
            asm volatile("cp.async.wait_group 1;" ::: "memory");
        } else {
            asm volatile("cp.async.wait_group 0;" ::: "memory");
        }
        __syncthreads();

        const uint32_t o = sb + (c & 1) * S_BUF;
#pragma unroll
        for (int ks = 0; ks < 2; ks++) {
            const uint32_t kofs = ks * 32 + a_kb;     // bytes within 64B k-row
            uint32_t ah[2][4], al_[2][4];
#pragma unroll
            for (int mi = 0; mi < 2; mi++) {
                ldsm4(ah[mi],  o + S_AH + (a_row + mi * 16) * 80 + kofs);
                ldsm4(al_[mi], o + S_AL + (a_row + mi * 16) * 80 + kofs);
            }
            const uint32_t bkofs = ks * 32 + b_kb;
            uint32_t bh[8][2], bl[8][2];
#pragma unroll
            for (int nj = 0; nj < 8; nj += 2) {
                uint32_t t4[4];
                ldsm4(t4, o + S_BH + (b_n + nj * 8) * 80 + bkofs);
                bh[nj][0] = t4[0]; bh[nj][1] = t4[1];
                bh[nj + 1][0] = t4[2]; bh[nj + 1][1] = t4[3];
                ldsm4(t4, o + S_BL + (b_n + nj * 8) * 80 + bkofs);
                bl[nj][0] = t4[0]; bl[nj][1] = t4[1];
                bl[nj + 1][0] = t4[2]; bl[nj + 1][1] = t4[3];
            }
#pragma unroll
            for (int mi = 0; mi < 2; mi++)
#pragma unroll
                for (int ni = 0; ni < 8; ni++) {
                    mma16816(acc[mi][ni], ah[mi], bh[ni]);
                    mma16816(acc[mi][ni], ah[mi], bl[ni]);
                    mma16816(acc[mi][ni], al_[mi], bh[ni]);
                }
        }
        __syncthreads();
    }

    // epilogue: bias (+relu), fp32 stores
    const int gid = l >> 2, tig = l & 3;
#pragma unroll
    for (int mi = 0; mi < 2; mi++) {
        const int row0 = m0 + wm * 32 + mi * 16 + gid;
#pragma unroll
        for (int ni = 0; ni < 8; ni++) {
            const int col = n0 + wn * 64 + ni * 8 + tig * 2;
            float b0 = bias[col], b1 = bias[col + 1];
            float v0 = acc[mi][ni][0] + b0;
            float v1 = acc[mi][ni][1] + b1;
            float v2 = acc[mi][ni][2] + b0;
            float v3 = acc[mi][ni][3] + b1;
            if (relu) {
                v0 = fmaxf(v0, 0.0f); v1 = fmaxf(v1, 0.0f);
                v2 = fmaxf(v2, 0.0f); v3 = fmaxf(v3, 0.0f);
            }
            float2 p0 = {v0, v1}, p1 = {v2, v3};
            *(float2*)(C + (size_t)row0 * N + col) = p0;
            *(float2*)(C + (size_t)(row0 + 8) * N + col) = p1;
        }
    }
}

// ---------------- embedding + positional encoding ---------------------------
__global__ void embed_kernel(const int* __restrict__ src,
                             const float* __restrict__ emb,
                             const float* __restrict__ pe,
                             float* __restrict__ x) {
    int row = blockIdx.x;
    int s = row & (SEQ - 1);
    int tok = src[row];
    const float* erow = emb + (size_t)tok * D_MODEL;
    const float* prow = pe + (size_t)s * D_MODEL;
    float* xrow = x + (size_t)row * D_MODEL;
    for (int d = threadIdx.x; d < D_MODEL; d += blockDim.x)
        xrow[d] = erow[d] * 32.0f + prow[d];
}

// ---------------- fused attention: one block per (b,h,q) --------------------
__global__ __launch_bounds__(128)
void attn_kernel(const float* __restrict__ Q,
                 const float* __restrict__ K,
                 const float* __restrict__ V,
                 const int* __restrict__ mask,
                 float* __restrict__ O) {
    const int q = blockIdx.x;
    const int h = blockIdx.y;
    const int b = blockIdx.z;
    const int tid = threadIdx.x;

    __shared__ float qv[D_K];
    __shared__ float sc[SEQ];
    __shared__ float red[128];

    const float* qrow = Q + ((size_t)(b * SEQ + q)) * D_MODEL + h * D_K;
    if (tid < D_K) qv[tid] = qrow[tid];
    __syncthreads();

    const int* mrow = mask + (size_t)b * SEQ;

    float lmax = -1e30f;
    for (int k = tid; k < SEQ; k += 128) {
        const float* krow = K + ((size_t)(b * SEQ + k)) * D_MODEL + h * D_K;
        float s = 0.0f;
#pragma unroll
        for (int d = 0; d < D_K; d += 4) {
            float4 kv = *(const float4*)(krow + d);
            s = fmaf(qv[d], kv.x, s);
            s = fmaf(qv[d + 1], kv.y, s);
            s = fmaf(qv[d + 2], kv.z, s);
            s = fmaf(qv[d + 3], kv.w, s);
        }
        s *= 0.125f;
        if (mrow[k] == 0) s = -1e9f;
        sc[k] = s;
        lmax = fmaxf(lmax, s);
    }
    red[tid] = lmax;
    __syncthreads();
    for (int off = 64; off > 0; off >>= 1) {
        if (tid < off) red[tid] = fmaxf(red[tid], red[tid + off]);
        __syncthreads();
    }
    float m = red[0];
    __syncthreads();

    float lsum = 0.0f;
    for (int k = tid; k < SEQ; k += 128) {
        float e = __expf(sc[k] - m);
        sc[k] = e;
        lsum += e;
    }
    red[tid] = lsum;
    __syncthreads();
    for (int off = 64; off > 0; off >>= 1) {
        if (tid < off) red[tid] += red[tid + off];
        __syncthreads();
    }
    float inv = 1.0f / red[0];
    __syncthreads();

    const int d = tid & 63;
    const int half = tid >> 6;
    float accv = 0.0f;
    const float* Vb = V + ((size_t)(b * SEQ)) * D_MODEL + h * D_K + d;
    for (int k = half * 512; k < half * 512 + 512; k++)
        accv = fmaf(sc[k], Vb[(size_t)k * D_MODEL], accv);
    red[tid] = accv;
    __syncthreads();
    if (half == 0)
        O[((size_t)(b * SEQ + q)) * D_MODEL + h * D_K + d] =
            (red[tid] + red[tid + 64]) * inv;
}

// ---------------- fused residual add + LayerNorm ----------------------------
__global__ __launch_bounds__(256)
void add_ln_kernel(const float* __restrict__ x,
                   const float* __restrict__ r,
                   const float* __restrict__ g,
                   const float* __restrict__ bta,
                   float* __restrict__ y) {
    const int row = blockIdx.x;
    const int tid = threadIdx.x;
    const float* xr = x + (size_t)row * D_MODEL;
    const float* rr = r + (size_t)row * D_MODEL;
    float* yr = y + (size_t)row * D_MODEL;

    float vals[4];
    float s = 0.0f, ss = 0.0f;
#pragma unroll
    for (int i = 0; i < 4; i++) {
        int c = tid + 256 * i;
        float v = xr[c] + rr[c];
        vals[i] = v;
        s += v;
        ss = fmaf(v, v, ss);
    }
    __shared__ float rs[256], rss[256];
    rs[tid] = s; rss[tid] = ss;
    __syncthreads();
    for (int off = 128; off > 0; off >>= 1) {
        if (tid < off) { rs[tid] += rs[tid + off]; rss[tid] += rss[tid + off]; }
        __syncthreads();
    }
    float mean = rs[0] * (1.0f / D_MODEL);
    float var = rss[0] * (1.0f / D_MODEL) - mean * mean;
    float inv = rsqrtf(var + 1e-5f);
#pragma unroll
    for (int i = 0; i < 4; i++) {
        int c = tid + 256 * i;
        yr[c] = (vals[i] - mean) * inv * g[c] + bta[c];
    }
}

// ---------------- host orchestration ---------------------------------------
extern "C" void kernel_launch(void* const* d_in, const int* in_sizes, int n_in,
                              void* d_out, int out_size) {
    const int*   src  = (const int*)d_in[0];
    const int*   mask = (const int*)d_in[1];
    const float* emb  = (const float*)d_in[2];
    const float* pe   = (const float*)d_in[3];
    const float* wq = (const float*)d_in[4];
    const float* bq = (const float*)d_in[5];
    const float* wk = (const float*)d_in[6];
    const float* bk = (const float*)d_in[7];
    const float* wv = (const float*)d_in[8];
    const float* bv = (const float*)d_in[9];
    const float* wo = (const float*)d_in[10];
    const float* bo = (const float*)d_in[11];
    const float* w1 = (const float*)d_in[12];
    const float* b1 = (const float*)d_in[13];
    const float* w2 = (const float*)d_in[14];
    const float* b2 = (const float*)d_in[15];
    const float* g1  = (const float*)d_in[16];
    const float* be1 = (const float*)d_in[17];
    const float* g2  = (const float*)d_in[18];
    const float* be2 = (const float*)d_in[19];
    float* out = (float*)d_out;

    float *px, *pq, *pk, *pv, *pa, *pt, *ph;
    cudaGetSymbolAddress((void**)&px, g_x);
    cudaGetSymbolAddress((void**)&pq, g_q);
    cudaGetSymbolAddress((void**)&pk, g_k);
    cudaGetSymbolAddress((void**)&pv, g_v);
    cudaGetSymbolAddress((void**)&pa, g_a);
    cudaGetSymbolAddress((void**)&pt, g_t);
    cudaGetSymbolAddress((void**)&ph, g_h);

    __nv_bfloat16 *ah, *al;
    cudaGetSymbolAddress((void**)&ah, g_ah);
    cudaGetSymbolAddress((void**)&al, g_al);

    __nv_bfloat16 *wqt_h, *wqt_l, *wkt_h, *wkt_l, *wvt_h, *wvt_l, *wot_h, *wot_l;
    __nv_bfloat16 *w1t_h, *w1t_l, *w2t_h, *w2t_l;
    cudaGetSymbolAddress((void**)&wqt_h, g_wqt_h);
    cudaGetSymbolAddress((void**)&wqt_l, g_wqt_l);
    cudaGetSymbolAddress((void**)&wkt_h, g_wkt_h);
    cudaGetSymbolAddress((void**)&wkt_l, g_wkt_l);
    cudaGetSymbolAddress((void**)&wvt_h, g_wvt_h);
    cudaGetSymbolAddress((void**)&wvt_l, g_wvt_l);
    cudaGetSymbolAddress((void**)&wot_h, g_wot_h);
    cudaGetSymbolAddress((void**)&wot_l, g_wot_l);
    cudaGetSymbolAddress((void**)&w1t_h, g_w1t_h);
    cudaGetSymbolAddress((void**)&w1t_l, g_w1t_l);
    cudaGetSymbolAddress((void**)&w2t_h, g_w2t_h);
    cudaGetSymbolAddress((void**)&w2t_l, g_w2t_l);

    static int smem_set = 0;
    if (!smem_set) {
        cudaFuncSetAttribute(gemm_tc, cudaFuncAttributeMaxDynamicSharedMemorySize,
                             GEMM_SMEM_BYTES);
        smem_set = 1;
    }

    // weight prep: transpose + bf16 split, all layers
    dim3 tblk(32, 8);
    transpose_split_kernel<<<dim3(32, 32, 6), tblk>>>(wq, wqt_h, wqt_l, 1024, 1024);
    transpose_split_kernel<<<dim3(32, 32, 6), tblk>>>(wk, wkt_h, wkt_l, 1024, 1024);
    transpose_split_kernel<<<dim3(32, 32, 6), tblk>>>(wv, wvt_h, wvt_l, 1024, 1024);
    transpose_split_kernel<<<dim3(32, 32, 6), tblk>>>(wo, wot_h, wot_l, 1024, 1024);
    transpose_split_kernel<<<dim3(128, 32, 6), tblk>>>(w1, w1t_h, w1t_l, 1024, 4096);
    transpose_split_kernel<<<dim3(32, 128, 6), tblk>>>(w2, w2t_h, w2t_l, 4096, 1024);

    embed_kernel<<<ROWS, 256>>>(src, emb, pe, px);

    const int n4_d = ROWS * D_MODEL / 4;    // fp32->bf16 split sizes (float4 units)
    const int n4_f = ROWS * D_FF / 4;

    dim3 g_dd(D_MODEL / 128, ROWS / 128);   // (8, 32)
    dim3 g_ff(D_FF / 128,    ROWS / 128);   // (32, 32)
    dim3 attn_grid(SEQ, N_HEADS, BATCH);

    for (int l = 0; l < N_LAYERS; l++) {
        size_t wofs  = (size_t)l * 1024 * 1024;
        size_t bofs  = (size_t)l * D_MODEL;
        size_t wfofs = (size_t)l * 4096 * 1024;
        size_t b1ofs = (size_t)l * D_FF;

        split_a_kernel<<<n4_d / 256, 256>>>(px, ah, al, n4_d);
        gemm_tc<<<g_dd, 256, GEMM_SMEM_BYTES>>>(ah, al, wqt_h + wofs, wqt_l + wofs,
                                                bq + bofs, pq, ROWS, D_MODEL, D_MODEL, 0);
        gemm_tc<<<g_dd, 256, GEMM_SMEM_BYTES>>>(ah, al, wkt_h + wofs, wkt_l + wofs,
                                                bk + bofs, pk, ROWS, D_MODEL, D_MODEL, 0);
        gemm_tc<<<g_dd, 256, GEMM_SMEM_BYTES>>>(ah, al, wvt_h + wofs, wvt_l + wofs,
                                                bv + bofs, pv, ROWS, D_MODEL, D_MODEL, 0);

        attn_kernel<<<attn_grid, 128>>>(pq, pk, pv, mask, pa);

        split_a_kernel<<<n4_d / 256, 256>>>(pa, ah, al, n4_d);
        gemm_tc<<<g_dd, 256, GEMM_SMEM_BYTES>>>(ah, al, wot_h + wofs, wot_l + wofs,
                                                bo + bofs, pt, ROWS, D_MODEL, D_MODEL, 0);
        add_ln_kernel<<<ROWS, 256>>>(px, pt, g1 + bofs, be1 + bofs, px);

        split_a_kernel<<<n4_d / 256, 256>>>(px, ah, al, n4_d);
        gemm_tc<<<g_ff, 256, GEMM_SMEM_BYTES>>>(ah, al, w1t_h + wfofs, w1t_l + wfofs,
                                                b1 + b1ofs, ph, ROWS, D_FF, D_MODEL, 1);
        split_a_kernel<<<n4_f / 256, 256>>>(ph, ah, al, n4_f);
        gemm_tc<<<g_dd, 256, GEMM_SMEM_BYTES>>>(ah, al, w2t_h + wfofs, w2t_l + wfofs,
                                                b2 + bofs, pt, ROWS, D_MODEL, D_FF, 0);
        add_ln_kernel<<<ROWS, 256>>>(px, pt, g2 + bofs, be2 + bofs, px);
    }

    cudaMemcpyAsync(out, px, (size_t)ROWS * D_MODEL * sizeof(float),
                    cudaMemcpyDeviceToDevice);
}

// round 6
// speedup vs baseline: 3.6385x; 2.9146x over previous
#include <cuda_runtime.h>
#include <cuda_bf16.h>
#include <math.h>
#include <stdint.h>

#define D_MODEL 1024
#define N_HEADS 16
#define D_K 64
#define D_FF 4096
#define N_LAYERS 6
#define BATCH 4
#define SEQ 1024
#define ROWS (BATCH * SEQ)   // 4096

// ---------------- scratch (device globals; no allocation allowed) ----------
__device__ float g_x[ROWS * D_MODEL];
__device__ float g_q[ROWS * D_MODEL];
__device__ float g_k[ROWS * D_MODEL];
__device__ float g_v[ROWS * D_MODEL];
__device__ float g_a[ROWS * D_MODEL];
__device__ float g_t[ROWS * D_MODEL];
__device__ float g_h[ROWS * D_FF];

// activation split buffers (max K = 4096)
__device__ __nv_bfloat16 g_ah[(size_t)ROWS * D_FF];
__device__ __nv_bfloat16 g_al[(size_t)ROWS * D_FF];

// transposed + split weights: [N,K] K-major bf16, hi and lo parts
__device__ __nv_bfloat16 g_wqt_h[6u*1024*1024], g_wqt_l[6u*1024*1024];
__device__ __nv_bfloat16 g_wkt_h[6u*1024*1024], g_wkt_l[6u*1024*1024];
__device__ __nv_bfloat16 g_wvt_h[6u*1024*1024], g_wvt_l[6u*1024*1024];
__device__ __nv_bfloat16 g_wot_h[6u*1024*1024], g_wot_l[6u*1024*1024];
__device__ __nv_bfloat16 g_w1t_h[6u*4096*1024], g_w1t_l[6u*4096*1024];
__device__ __nv_bfloat16 g_w2t_h[6u*4096*1024], g_w2t_l[6u*4096*1024];

// ---------------- PTX helpers ------------------------------------------------
__device__ __forceinline__ uint32_t smem_u32(const void* p) {
    uint32_t a;
    asm("{ .reg .u64 t; cvta.to.shared.u64 t, %1; cvt.u32.u64 %0, t; }"
        : "=r"(a) : "l"(p));
    return a;
}

__device__ __forceinline__ void cp16(uint32_t s, const void* g) {
    asm volatile("cp.async.cg.shared.global [%0], [%1], 16;"
                 :: "r"(s), "l"(g) : "memory");
}

__device__ __forceinline__ void ldsm4(uint32_t* r, uint32_t addr) {
    asm volatile("ldmatrix.sync.aligned.m8n8.x4.shared.b16 {%0,%1,%2,%3}, [%4];"
                 : "=r"(r[0]), "=r"(r[1]), "=r"(r[2]), "=r"(r[3]) : "r"(addr));
}

__device__ __forceinline__ void mma16816(float* c, const uint32_t* a,
                                         const uint32_t* b) {
    asm volatile(
        "mma.sync.aligned.m16n8k16.row.col.f32.bf16.bf16.f32 "
        "{%0,%1,%2,%3}, {%4,%5,%6,%7}, {%8,%9}, {%0,%1,%2,%3};"
        : "+f"(c[0]), "+f"(c[1]), "+f"(c[2]), "+f"(c[3])
        : "r"(a[0]), "r"(a[1]), "r"(a[2]), "r"(a[3]), "r"(b[0]), "r"(b[1]));
}

// ---------------- weight transpose + bf16 hi/lo split -----------------------
__global__ void transpose_split_kernel(const float* __restrict__ W,
                                       __nv_bfloat16* __restrict__ Th,
                                       __nv_bfloat16* __restrict__ Tl,
                                       int K, int N) {
    __shared__ float t[32][33];
    size_t lofs = (size_t)blockIdx.z * K * N;
    const float* Wl = W + lofs;
    int n0 = blockIdx.x * 32, k0 = blockIdx.y * 32;
    int tx = threadIdx.x, ty = threadIdx.y;
#pragma unroll
    for (int i = ty; i < 32; i += 8)
        t[i][tx] = Wl[(size_t)(k0 + i) * N + n0 + tx];
    __syncthreads();
#pragma unroll
    for (int i = ty; i < 32; i += 8) {
        float v = t[tx][i];
        __nv_bfloat16 h = __float2bfloat16(v);
        float lo = v - __bfloat162float(h);
        size_t o = lofs + (size_t)(n0 + i) * K + k0 + tx;
        Th[o] = h;
        Tl[o] = __float2bfloat16(lo);
    }
}

// ---------------- activation split: fp32 -> bf16 hi/lo ----------------------
__global__ __launch_bounds__(256)
void split_a_kernel(const float* __restrict__ X,
                    __nv_bfloat16* __restrict__ H,
                    __nv_bfloat16* __restrict__ L, int n4) {
    int i = blockIdx.x * 256 + threadIdx.x;
    if (i >= n4) return;
    float4 v = ((const float4*)X)[i];
    __nv_bfloat162 h0 = __floats2bfloat162_rn(v.x, v.y);
    __nv_bfloat162 h1 = __floats2bfloat162_rn(v.z, v.w);
    float2 f0 = __bfloat1622float2(h0);
    float2 f1 = __bfloat1622float2(h1);
    __nv_bfloat162 l0 = __floats2bfloat162_rn(v.x - f0.x, v.y - f0.y);
    __nv_bfloat162 l1 = __floats2bfloat162_rn(v.z - f1.x, v.w - f1.y);
    ((__nv_bfloat162*)H)[2 * i] = h0;
    ((__nv_bfloat162*)H)[2 * i + 1] = h1;
    ((__nv_bfloat162*)L)[2 * i] = l0;
    ((__nv_bfloat162*)L)[2 * i + 1] = l1;
}

// ---------------- mma.sync bf16 split-3 GEMM --------------------------------
#define S_AH 0
#define S_AL 10240
#define S_BH 20480
#define S_BL 30720
#define S_BUF 40960
#define GEMM_SMEM_BYTES (2 * S_BUF)   // 81920

__global__ __launch_bounds__(256, 1)
void gemm_tc(const __nv_bfloat16* __restrict__ Ah,
             const __nv_bfloat16* __restrict__ Al,
             const __nv_bfloat16* __restrict__ Bh,
             const __nv_bfloat16* __restrict__ Bl,
             const float* __restrict__ bias,
             float* __restrict__ C,
             int M, int N, int K, int relu) {
    extern __shared__ char sm[];
    const uint32_t sb = smem_u32(sm);

    const int tid = threadIdx.x;
    const int l = tid & 31, w = tid >> 5;
    const int wm = w & 3, wn = w >> 2;
    const int m0 = blockIdx.y * 128, n0 = blockIdx.x * 128;

    const int lr = tid >> 1;
    const int lkc = (tid & 1) * 2;

    const __nv_bfloat16* agh = Ah + (size_t)(m0 + lr) * K + lkc * 8;
    const __nv_bfloat16* agl = Al + (size_t)(m0 + lr) * K + lkc * 8;
    const __nv_bfloat16* bgh = Bh + (size_t)(n0 + lr) * K + lkc * 8;
    const __nv_bfloat16* bgl = Bl + (size_t)(n0 + lr) * K + lkc * 8;
    const uint32_t srow = lr * 80 + lkc * 16;

    auto issue = [&](int c, int b) {
        const uint32_t o = sb + b * S_BUF + srow;
        const size_t go = (size_t)c * 32;
        cp16(o + S_AH,      agh + go);
        cp16(o + S_AH + 16, agh + go + 8);
        cp16(o + S_AL,      agl + go);
        cp16(o + S_AL + 16, agl + go + 8);
        cp16(o + S_BH,      bgh + go);
        cp16(o + S_BH + 16, bgh + go + 8);
        cp16(o + S_BL,      bgl + go);
        cp16(o + S_BL + 16, bgl + go + 8);
        asm volatile("cp.async.commit_group;" ::: "memory");
    };

    float acc[2][8][4] = {};

    const int NCk = K >> 5;
    issue(0, 0);

    const int a_row = wm * 32 + (l & 15);
    const int a_kb = ((l >> 4) << 3) * 2;
    const int b_n = wn * 64 + ((l >> 4) << 3) + (l & 7);
    const int b_kb = (((l >> 3) & 1) << 3) * 2;

    for (int c = 0; c < NCk; c++) {
        if (c + 1 < NCk) {
            issue(c + 1, (c + 1) & 1);
            asm volatile("cp.async.wait_group 1;" ::: "memory");
        } else {
            asm volatile("cp.async.wait_group 0;" ::: "memory");
        }
        __syncthreads();

        const uint32_t o = sb + (c & 1) * S_BUF;
#pragma unroll
        for (int ks = 0; ks < 2; ks++) {
            const uint32_t kofs = ks * 32 + a_kb;
            uint32_t ah[2][4], al_[2][4];
#pragma unroll
            for (int mi = 0; mi < 2; mi++) {
                ldsm4(ah[mi],  o + S_AH + (a_row + mi * 16) * 80 + kofs);
                ldsm4(al_[mi], o + S_AL + (a_row + mi * 16) * 80 + kofs);
            }
            const uint32_t bkofs = ks * 32 + b_kb;
            uint32_t bh[8][2], bl[8][2];
#pragma unroll
            for (int nj = 0; nj < 8; nj += 2) {
                uint32_t t4[4];
                ldsm4(t4, o + S_BH + (b_n + nj * 8) * 80 + bkofs);
                bh[nj][0] = t4[0]; bh[nj][1] = t4[1];
                bh[nj + 1][0] = t4[2]; bh[nj + 1][1] = t4[3];
                ldsm4(t4, o + S_BL + (b_n + nj * 8) * 80 + bkofs);
                bl[nj][0] = t4[0]; bl[nj][1] = t4[1];
                bl[nj + 1][0] = t4[2]; bl[nj + 1][1] = t4[3];
            }
#pragma unroll
            for (int mi = 0; mi < 2; mi++)
#pragma unroll
                for (int ni = 0; ni < 8; ni++) {
                    mma16816(acc[mi][ni], ah[mi], bh[ni]);
                    mma16816(acc[mi][ni], ah[mi], bl[ni]);
                    mma16816(acc[mi][ni], al_[mi], bh[ni]);
                }
        }
        __syncthreads();
    }

    const int gid = l >> 2, tig = l & 3;
#pragma unroll
    for (int mi = 0; mi < 2; mi++) {
        const int row0 = m0 + wm * 32 + mi * 16 + gid;
#pragma unroll
        for (int ni = 0; ni < 8; ni++) {
            const int col = n0 + wn * 64 + ni * 8 + tig * 2;
            float b0 = bias[col], b1 = bias[col + 1];
            float v0 = acc[mi][ni][0] + b0;
            float v1 = acc[mi][ni][1] + b1;
            float v2 = acc[mi][ni][2] + b0;
            float v3 = acc[mi][ni][3] + b1;
            if (relu) {
                v0 = fmaxf(v0, 0.0f); v1 = fmaxf(v1, 0.0f);
                v2 = fmaxf(v2, 0.0f); v3 = fmaxf(v3, 0.0f);
            }
            float2 p0 = {v0, v1}, p1 = {v2, v3};
            *(float2*)(C + (size_t)row0 * N + col) = p0;
            *(float2*)(C + (size_t)(row0 + 8) * N + col) = p1;
        }
    }
}

// ---------------- embedding + positional encoding ---------------------------
__global__ void embed_kernel(const int* __restrict__ src,
                             const float* __restrict__ emb,
                             const float* __restrict__ pe,
                             float* __restrict__ x) {
    int row = blockIdx.x;
    int s = row & (SEQ - 1);
    int tok = src[row];
    const float* erow = emb + (size_t)tok * D_MODEL;
    const float* prow = pe + (size_t)s * D_MODEL;
    float* xrow = x + (size_t)row * D_MODEL;
    for (int d = threadIdx.x; d < D_MODEL; d += blockDim.x)
        xrow[d] = erow[d] * 32.0f + prow[d];
}

// ---------------- flash-style tiled attention --------------------------------
// block = (qt, h, b): 64 q-rows, loop over 16 k-tiles of 64.
// 256 threads: g = tid&7 (8 col/dim groups), qp = tid>>3 (rows qp, qp+32).
#define ATT_STRIDE 68
#define ATT_SMEM_BYTES ((4 * 64 * ATT_STRIDE) * 4 + 256)

__global__ __launch_bounds__(256, 2)
void attn_tile_kernel(const float* __restrict__ Q,
                      const float* __restrict__ Kp,
                      const float* __restrict__ Vp,
                      const int* __restrict__ mask,
                      float* __restrict__ Out) {
    extern __shared__ float shm[];
    float* Qs = shm;                            // [64][68]
    float* Ks = shm + 64 * ATT_STRIDE;
    float* Ps = shm + 2 * 64 * ATT_STRIDE;
    float* Vs = shm + 3 * 64 * ATT_STRIDE;
    int*   ms = (int*)(shm + 4 * 64 * ATT_STRIDE);

    const int tid = threadIdx.x;
    const int g = tid & 7;
    const int qp = tid >> 3;                    // 0..31
    const int qt = blockIdx.x, h = blockIdx.y, b = blockIdx.z;

    const int lrow = tid >> 2, lcol = (tid & 3) * 16;
    const float* Qg = Q + ((size_t)(b * SEQ + qt * 64)) * D_MODEL + h * D_K;
    const float* Kg = Kp + ((size_t)(b * SEQ)) * D_MODEL + h * D_K;
    const float* Vg = Vp + ((size_t)(b * SEQ)) * D_MODEL + h * D_K;

#pragma unroll
    for (int c = 0; c < 16; c += 4)
        *(float4*)&Qs[lrow * ATT_STRIDE + lcol + c] =
            *(const float4*)(Qg + (size_t)lrow * D_MODEL + lcol + c);

    float m0 = -1e30f, m1 = -1e30f, l0 = 0.0f, l1 = 0.0f;
    float O0[8] = {0}, O1[8] = {0};

    for (int kt = 0; kt < SEQ / 64; kt++) {
        __syncthreads();
#pragma unroll
        for (int c = 0; c < 16; c += 4) {
            *(float4*)&Ks[lrow * ATT_STRIDE + lcol + c] =
                *(const float4*)(Kg + (size_t)(kt * 64 + lrow) * D_MODEL + lcol + c);
            *(float4*)&Vs[lrow * ATT_STRIDE + lcol + c] =
                *(const float4*)(Vg + (size_t)(kt * 64 + lrow) * D_MODEL + lcol + c);
        }
        if (tid < 64) ms[tid] = mask[b * SEQ + kt * 64 + tid];
        __syncthreads();

        float s0[8] = {0}, s1[8] = {0};
#pragma unroll
        for (int d = 0; d < 64; d += 4) {
            float4 qa = *(const float4*)&Qs[qp * ATT_STRIDE + d];
            float4 qb = *(const float4*)&Qs[(qp + 32) * ATT_STRIDE + d];
#pragma unroll
            for (int jj = 0; jj < 8; jj++) {
                float4 kv = *(const float4*)&Ks[(g + 8 * jj) * ATT_STRIDE + d];
                s0[jj] = fmaf(qa.x, kv.x, fmaf(qa.y, kv.y,
                          fmaf(qa.z, kv.z, fmaf(qa.w, kv.w, s0[jj]))));
                s1[jj] = fmaf(qb.x, kv.x, fmaf(qb.y, kv.y,
                          fmaf(qb.z, kv.z, fmaf(qb.w, kv.w, s1[jj]))));
            }
        }

        float tm0 = -1e30f, tm1 = -1e30f;
#pragma unroll
        for (int jj = 0; jj < 8; jj++) {
            int msk = ms[g + 8 * jj];
            float a0 = msk ? s0[jj] * 0.125f : -1e9f;
            float a1 = msk ? s1[jj] * 0.125f : -1e9f;
            s0[jj] = a0; s1[jj] = a1;
            tm0 = fmaxf(tm0, a0); tm1 = fmaxf(tm1, a1);
        }
#pragma unroll
        for (int o = 1; o < 8; o <<= 1) {
            tm0 = fmaxf(tm0, __shfl_xor_sync(0xffffffffu, tm0, o));
            tm1 = fmaxf(tm1, __shfl_xor_sync(0xffffffffu, tm1, o));
        }
        float mn0 = fmaxf(m0, tm0), mn1 = fmaxf(m1, tm1);
        float sc0 = __expf(m0 - mn0), sc1 = __expf(m1 - mn1);
        m0 = mn0; m1 = mn1;

        float ps0 = 0.0f, ps1 = 0.0f;
#pragma unroll
        for (int jj = 0; jj < 8; jj++) {
            float p0 = __expf(s0[jj] - mn0);
            float p1 = __expf(s1[jj] - mn1);
            ps0 += p0; ps1 += p1;
            Ps[qp * ATT_STRIDE + g + 8 * jj] = p0;
            Ps[(qp + 32) * ATT_STRIDE + g + 8 * jj] = p1;
        }
#pragma unroll
        for (int o = 1; o < 8; o <<= 1) {
            ps0 += __shfl_xor_sync(0xffffffffu, ps0, o);
            ps1 += __shfl_xor_sync(0xffffffffu, ps1, o);
        }
        l0 = l0 * sc0 + ps0;
        l1 = l1 * sc1 + ps1;
#pragma unroll
        for (int c = 0; c < 8; c++) { O0[c] *= sc0; O1[c] *= sc1; }
        __syncwarp();

#pragma unroll 4
        for (int j = 0; j < 64; j++) {
            float p0 = Ps[qp * ATT_STRIDE + j];
            float p1 = Ps[(qp + 32) * ATT_STRIDE + j];
            float4 va = *(const float4*)&Vs[j * ATT_STRIDE + 4 * g];
            float4 vb = *(const float4*)&Vs[j * ATT_STRIDE + 32 + 4 * g];
            O0[0] = fmaf(p0, va.x, O0[0]); O0[1] = fmaf(p0, va.y, O0[1]);
            O0[2] = fmaf(p0, va.z, O0[2]); O0[3] = fmaf(p0, va.w, O0[3]);
            O0[4] = fmaf(p0, vb.x, O0[4]); O0[5] = fmaf(p0, vb.y, O0[5]);
            O0[6] = fmaf(p0, vb.z, O0[6]); O0[7] = fmaf(p0, vb.w, O0[7]);
            O1[0] = fmaf(p1, va.x, O1[0]); O1[1] = fmaf(p1, va.y, O1[1]);
            O1[2] = fmaf(p1, va.z, O1[2]); O1[3] = fmaf(p1, va.w, O1[3]);
            O1[4] = fmaf(p1, vb.x, O1[4]); O1[5] = fmaf(p1, vb.y, O1[5]);
            O1[6] = fmaf(p1, vb.z, O1[6]); O1[7] = fmaf(p1, vb.w, O1[7]);
        }
    }

    const float inv0 = 1.0f / l0, inv1 = 1.0f / l1;
    float* or0 = Out + ((size_t)(b * SEQ + qt * 64 + qp)) * D_MODEL + h * D_K;
    float* or1 = Out + ((size_t)(b * SEQ + qt * 64 + qp + 32)) * D_MODEL + h * D_K;
    float4 w;
    w.x = O0[0] * inv0; w.y = O0[1] * inv0; w.z = O0[2] * inv0; w.w = O0[3] * inv0;
    *(float4*)(or0 + 4 * g) = w;
    w.x = O0[4] * inv0; w.y = O0[5] * inv0; w.z = O0[6] * inv0; w.w = O0[7] * inv0;
    *(float4*)(or0 + 32 + 4 * g) = w;
    w.x = O1[0] * inv1; w.y = O1[1] * inv1; w.z = O1[2] * inv1; w.w = O1[3] * inv1;
    *(float4*)(or1 + 4 * g) = w;
    w.x = O1[4] * inv1; w.y = O1[5] * inv1; w.z = O1[6] * inv1; w.w = O1[7] * inv1;
    *(float4*)(or1 + 32 + 4 * g) = w;
}

// ---------------- fused residual add + LayerNorm ----------------------------
__global__ __launch_bounds__(256)
void add_ln_kernel(const float* __restrict__ x,
                   const float* __restrict__ r,
                   const float* __restrict__ g,
                   const float* __restrict__ bta,
                   float* __restrict__ y) {
    const int row = blockIdx.x;
    const int tid = threadIdx.x;
    const float* xr = x + (size_t)row * D_MODEL;
    const float* rr = r + (size_t)row * D_MODEL;
    float* yr = y + (size_t)row * D_MODEL;

    float vals[4];
    float s = 0.0f, ss = 0.0f;
#pragma unroll
    for (int i = 0; i < 4; i++) {
        int c = tid + 256 * i;
        float v = xr[c] + rr[c];
        vals[i] = v;
        s += v;
        ss = fmaf(v, v, ss);
    }
    __shared__ float rs[256], rss[256];
    rs[tid] = s; rss[tid] = ss;
    __syncthreads();
    for (int off = 128; off > 0; off >>= 1) {
        if (tid < off) { rs[tid] += rs[tid + off]; rss[tid] += rss[tid + off]; }
        __syncthreads();
    }
    float mean = rs[0] * (1.0f / D_MODEL);
    float var = rss[0] * (1.0f / D_MODEL) - mean * mean;
    float inv = rsqrtf(var + 1e-5f);
#pragma unroll
    for (int i = 0; i < 4; i++) {
        int c = tid + 256 * i;
        yr[c] = (vals[i] - mean) * inv * g[c] + bta[c];
    }
}

// ---------------- host orchestration ---------------------------------------
extern "C" void kernel_launch(void* const* d_in, const int* in_sizes, int n_in,
                              void* d_out, int out_size) {
    const int*   src  = (const int*)d_in[0];
    const int*   mask = (const int*)d_in[1];
    const float* emb  = (const float*)d_in[2];
    const float* pe   = (const float*)d_in[3];
    const float* wq = (const float*)d_in[4];
    const float* bq = (const float*)d_in[5];
    const float* wk = (const float*)d_in[6];
    const float* bk = (const float*)d_in[7];
    const float* wv = (const float*)d_in[8];
    const float* bv = (const float*)d_in[9];
    const float* wo = (const float*)d_in[10];
    const float* bo = (const float*)d_in[11];
    const float* w1 = (const float*)d_in[12];
    const float* b1 = (const float*)d_in[13];
    const float* w2 = (const float*)d_in[14];
    const float* b2 = (const float*)d_in[15];
    const float* g1  = (const float*)d_in[16];
    const float* be1 = (const float*)d_in[17];
    const float* g2  = (const float*)d_in[18];
    const float* be2 = (const float*)d_in[19];
    float* out = (float*)d_out;

    float *px, *pq, *pk, *pv, *pa, *pt, *ph;
    cudaGetSymbolAddress((void**)&px, g_x);
    cudaGetSymbolAddress((void**)&pq, g_q);
    cudaGetSymbolAddress((void**)&pk, g_k);
    cudaGetSymbolAddress((void**)&pv, g_v);
    cudaGetSymbolAddress((void**)&pa, g_a);
    cudaGetSymbolAddress((void**)&pt, g_t);
    cudaGetSymbolAddress((void**)&ph, g_h);

    __nv_bfloat16 *ah, *al;
    cudaGetSymbolAddress((void**)&ah, g_ah);
    cudaGetSymbolAddress((void**)&al, g_al);

    __nv_bfloat16 *wqt_h, *wqt_l, *wkt_h, *wkt_l, *wvt_h, *wvt_l, *wot_h, *wot_l;
    __nv_bfloat16 *w1t_h, *w1t_l, *w2t_h, *w2t_l;
    cudaGetSymbolAddress((void**)&wqt_h, g_wqt_h);
    cudaGetSymbolAddress((void**)&wqt_l, g_wqt_l);
    cudaGetSymbolAddress((void**)&wkt_h, g_wkt_h);
    cudaGetSymbolAddress((void**)&wkt_l, g_wkt_l);
    cudaGetSymbolAddress((void**)&wvt_h, g_wvt_h);
    cudaGetSymbolAddress((void**)&wvt_l, g_wvt_l);
    cudaGetSymbolAddress((void**)&wot_h, g_wot_h);
    cudaGetSymbolAddress((void**)&wot_l, g_wot_l);
    cudaGetSymbolAddress((void**)&w1t_h, g_w1t_h);
    cudaGetSymbolAddress((void**)&w1t_l, g_w1t_l);
    cudaGetSymbolAddress((void**)&w2t_h, g_w2t_h);
    cudaGetSymbolAddress((void**)&w2t_l, g_w2t_l);

    static int attr_set = 0;
    if (!attr_set) {
        cudaFuncSetAttribute(gemm_tc, cudaFuncAttributeMaxDynamicSharedMemorySize,
                             GEMM_SMEM_BYTES);
        cudaFuncSetAttribute(attn_tile_kernel,
                             cudaFuncAttributeMaxDynamicSharedMemorySize,
                             ATT_SMEM_BYTES);
        attr_set = 1;
    }

    // weight prep: transpose + bf16 split, all layers
    dim3 tblk(32, 8);
    transpose_split_kernel<<<dim3(32, 32, 6), tblk>>>(wq, wqt_h, wqt_l, 1024, 1024);
    transpose_split_kernel<<<dim3(32, 32, 6), tblk>>>(wk, wkt_h, wkt_l, 1024, 1024);
    transpose_split_kernel<<<dim3(32, 32, 6), tblk>>>(wv, wvt_h, wvt_l, 1024, 1024);
    transpose_split_kernel<<<dim3(32, 32, 6), tblk>>>(wo, wot_h, wot_l, 1024, 1024);
    transpose_split_kernel<<<dim3(128, 32, 6), tblk>>>(w1, w1t_h, w1t_l, 1024, 4096);
    transpose_split_kernel<<<dim3(32, 128, 6), tblk>>>(w2, w2t_h, w2t_l, 4096, 1024);

    embed_kernel<<<ROWS, 256>>>(src, emb, pe, px);

    const int n4_d = ROWS * D_MODEL / 4;
    const int n4_f = ROWS * D_FF / 4;

    dim3 g_dd(D_MODEL / 128, ROWS / 128);   // (8, 32)
    dim3 g_ff(D_FF / 128,    ROWS / 128);   // (32, 32)
    dim3 attn_grid(SEQ / 64, N_HEADS, BATCH);

    for (int l = 0; l < N_LAYERS; l++) {
        size_t wofs  = (size_t)l * 1024 * 1024;
        size_t bofs  = (size_t)l * D_MODEL;
        size_t wfofs = (size_t)l * 4096 * 1024;
        size_t b1ofs = (size_t)l * D_FF;

        split_a_kernel<<<n4_d / 256, 256>>>(px, ah, al, n4_d);
        gemm_tc<<<g_dd, 256, GEMM_SMEM_BYTES>>>(ah, al, wqt_h + wofs, wqt_l + wofs,
                                                bq + bofs, pq, ROWS, D_MODEL, D_MODEL, 0);
        gemm_tc<<<g_dd, 256, GEMM_SMEM_BYTES>>>(ah, al, wkt_h + wofs, wkt_l + wofs,
                                                bk + bofs, pk, ROWS, D_MODEL, D_MODEL, 0);
        gemm_tc<<<g_dd, 256, GEMM_SMEM_BYTES>>>(ah, al, wvt_h + wofs, wvt_l + wofs,
                                                bv + bofs, pv, ROWS, D_MODEL, D_MODEL, 0);

        attn_tile_kernel<<<attn_grid, 256, ATT_SMEM_BYTES>>>(pq, pk, pv, mask, pa);

        split_a_kernel<<<n4_d / 256, 256>>>(pa, ah, al, n4_d);
        gemm_tc<<<g_dd, 256, GEMM_SMEM_BYTES>>>(ah, al, wot_h + wofs, wot_l + wofs,
                                                bo + bofs, pt, ROWS, D_MODEL, D_MODEL, 0);
        add_ln_kernel<<<ROWS, 256>>>(px, pt, g1 + bofs, be1 + bofs, px);

        split_a_kernel<<<n4_d / 256, 256>>>(px, ah, al, n4_d);
        gemm_tc<<<g_ff, 256, GEMM_SMEM_BYTES>>>(ah, al, w1t_h + wfofs, w1t_l + wfofs,
                                                b1 + b1ofs, ph, ROWS, D_FF, D_MODEL, 1);
        split_a_kernel<<<n4_f / 256, 256>>>(ph, ah, al, n4_f);
        gemm_tc<<<g_dd, 256, GEMM_SMEM_BYTES>>>(ah, al, w2t_h + wfofs, w2t_l + wfofs,
                                                b2 + bofs, pt, ROWS, D_MODEL, D_FF, 0);
        add_ln_kernel<<<ROWS, 256>>>(px, pt, g2 + bofs, be2 + bofs, px);
    }

    cudaMemcpyAsync(out, px, (size_t)ROWS * D_MODEL * sizeof(float),
                    cudaMemcpyDeviceToDevice);
}

// round 7
// speedup vs baseline: 3.7331x; 1.0260x over previous
#include <cuda_runtime.h>
#include <cuda_bf16.h>
#include <math.h>
#include <stdint.h>

#define D_MODEL 1024
#define N_HEADS 16
#define D_K 64
#define D_FF 4096
#define N_LAYERS 6
#define BATCH 4
#define SEQ 1024
#define ROWS (BATCH * SEQ)   // 4096

// ---------------- scratch (device globals; no allocation allowed) ----------
__device__ float g_x[ROWS * D_MODEL];                 // residual stream (fp32)
__device__ float g_qkv[(size_t)ROWS * 3 * D_MODEL];   // fused QKV output
__device__ float g_t[ROWS * D_MODEL];                 // pre-LN gemm output
__device__ __nv_bfloat16 g_ah[(size_t)ROWS * D_MODEL];  // activation hi
__device__ __nv_bfloat16 g_al[(size_t)ROWS * D_MODEL];  // activation lo
__device__ __nv_bfloat16 g_hh[(size_t)ROWS * D_FF];     // ffn hidden hi
__device__ __nv_bfloat16 g_hl[(size_t)ROWS * D_FF];     // ffn hidden lo

// transposed + split weights: [N,K] K-major bf16, hi and lo parts
__device__ __nv_bfloat16 g_wqkvt_h[6u*3072*1024], g_wqkvt_l[6u*3072*1024];
__device__ __nv_bfloat16 g_wot_h[6u*1024*1024],  g_wot_l[6u*1024*1024];
__device__ __nv_bfloat16 g_w1t_h[6u*4096*1024],  g_w1t_l[6u*4096*1024];
__device__ __nv_bfloat16 g_w2t_h[6u*4096*1024],  g_w2t_l[6u*4096*1024];
__device__ float g_bqkv[6 * 3072];

// ---------------- PTX helpers ------------------------------------------------
__device__ __forceinline__ uint32_t smem_u32(const void* p) {
    uint32_t a;
    asm("{ .reg .u64 t; cvta.to.shared.u64 t, %1; cvt.u32.u64 %0, t; }"
        : "=r"(a) : "l"(p));
    return a;
}

__device__ __forceinline__ void cp16(uint32_t s, const void* g) {
    asm volatile("cp.async.cg.shared.global [%0], [%1], 16;"
                 :: "r"(s), "l"(g) : "memory");
}

__device__ __forceinline__ void ldsm4(uint32_t* r, uint32_t addr) {
    asm volatile("ldmatrix.sync.aligned.m8n8.x4.shared.b16 {%0,%1,%2,%3}, [%4];"
                 : "=r"(r[0]), "=r"(r[1]), "=r"(r[2]), "=r"(r[3]) : "r"(addr));
}

__device__ __forceinline__ void mma16816(float* c, const uint32_t* a,
                                         const uint32_t* b) {
    asm volatile(
        "mma.sync.aligned.m16n8k16.row.col.f32.bf16.bf16.f32 "
        "{%0,%1,%2,%3}, {%4,%5,%6,%7}, {%8,%9}, {%0,%1,%2,%3};"
        : "+f"(c[0]), "+f"(c[1]), "+f"(c[2]), "+f"(c[3])
        : "r"(a[0]), "r"(a[1]), "r"(a[2]), "r"(a[3]), "r"(b[0]), "r"(b[1]));
}

// split a float4 into bf16 hi/lo pairs, store 8B each
__device__ __forceinline__ void store_split4(__nv_bfloat16* H, __nv_bfloat16* L,
                                             size_t idx, float4 v) {
    __nv_bfloat162 h0 = __floats2bfloat162_rn(v.x, v.y);
    __nv_bfloat162 h1 = __floats2bfloat162_rn(v.z, v.w);
    float2 f0 = __bfloat1622float2(h0);
    float2 f1 = __bfloat1622float2(h1);
    __nv_bfloat162 l0 = __floats2bfloat162_rn(v.x - f0.x, v.y - f0.y);
    __nv_bfloat162 l1 = __floats2bfloat162_rn(v.z - f1.x, v.w - f1.y);
    uint2 hh, ll;
    hh.x = *reinterpret_cast<uint32_t*>(&h0);
    hh.y = *reinterpret_cast<uint32_t*>(&h1);
    ll.x = *reinterpret_cast<uint32_t*>(&l0);
    ll.y = *reinterpret_cast<uint32_t*>(&l1);
    *(uint2*)(H + idx) = hh;
    *(uint2*)(L + idx) = ll;
}

// ---------------- weight transpose + bf16 hi/lo split -----------------------
// W: [L][K][N] -> Th/Tl: [L (lstride)][row_off + N rows][K] K-major
__global__ void transpose_split_kernel(const float* __restrict__ W,
                                       __nv_bfloat16* __restrict__ Th,
                                       __nv_bfloat16* __restrict__ Tl,
                                       int K, int N, size_t out_lstride,
                                       int row_off) {
    __shared__ float t[32][33];
    const float* Wl = W + (size_t)blockIdx.z * K * N;
    int n0 = blockIdx.x * 32, k0 = blockIdx.y * 32;
    int tx = threadIdx.x, ty = threadIdx.y;
#pragma unroll
    for (int i = ty; i < 32; i += 8)
        t[i][tx] = Wl[(size_t)(k0 + i) * N + n0 + tx];
    __syncthreads();
#pragma unroll
    for (int i = ty; i < 32; i += 8) {
        float v = t[tx][i];
        __nv_bfloat16 h = __float2bfloat16(v);
        float lo = v - __bfloat162float(h);
        size_t o = (size_t)blockIdx.z * out_lstride +
                   (size_t)(row_off + n0 + i) * K + k0 + tx;
        Th[o] = h;
        Tl[o] = __float2bfloat16(lo);
    }
}

__global__ void concat_bias_kernel(const float* __restrict__ bq,
                                   const float* __restrict__ bk,
                                   const float* __restrict__ bv,
                                   float* __restrict__ dst) {
    int l = blockIdx.y;
    int i = blockIdx.x * 256 + threadIdx.x;   // 0..3071
    float v;
    if (i < 1024) v = bq[l * 1024 + i];
    else if (i < 2048) v = bk[l * 1024 + i - 1024];
    else v = bv[l * 1024 + i - 2048];
    dst[l * 3072 + i] = v;
}

// ---------------- mma.sync bf16 split-3 GEMM --------------------------------
// C[M,N] = A[M,K] @ B[N,K]^T + bias. 3-stage cp.async pipeline, 1 sync/chunk.
// outmode 0: fp32 -> C;  outmode 1: bf16 hi/lo -> Hout/Lout.
#define S_AH 0
#define S_AL 10240
#define S_BH 20480
#define S_BL 30720
#define S_BUF 40960
#define GEMM_SMEM_BYTES (3 * S_BUF)   // 122880

__global__ __launch_bounds__(256, 1)
void gemm_tc(const __nv_bfloat16* __restrict__ Ah,
             const __nv_bfloat16* __restrict__ Al,
             const __nv_bfloat16* __restrict__ Bh,
             const __nv_bfloat16* __restrict__ Bl,
             const float* __restrict__ bias,
             float* __restrict__ C,
             __nv_bfloat16* __restrict__ Hout,
             __nv_bfloat16* __restrict__ Lout,
             int M, int N, int K, int relu, int outmode) {
    extern __shared__ char sm[];
    const uint32_t sb = smem_u32(sm);

    const int tid = threadIdx.x;
    const int l = tid & 31, w = tid >> 5;
    const int wm = w & 3, wn = w >> 2;
    const int m0 = blockIdx.y * 128, n0 = blockIdx.x * 128;

    const int lr = tid >> 1;
    const int lkc = (tid & 1) * 2;

    const __nv_bfloat16* agh = Ah + (size_t)(m0 + lr) * K + lkc * 8;
    const __nv_bfloat16* agl = Al + (size_t)(m0 + lr) * K + lkc * 8;
    const __nv_bfloat16* bgh = Bh + (size_t)(n0 + lr) * K + lkc * 8;
    const __nv_bfloat16* bgl = Bl + (size_t)(n0 + lr) * K + lkc * 8;
    const uint32_t srow = lr * 80 + lkc * 16;

    auto issue = [&](int c) {
        const uint32_t o = sb + (c % 3) * S_BUF + srow;
        const size_t go = (size_t)c * 32;
        cp16(o + S_AH,      agh + go);
        cp16(o + S_AH + 16, agh + go + 8);
        cp16(o + S_AL,      agl + go);
        cp16(o + S_AL + 16, agl + go + 8);
        cp16(o + S_BH,      bgh + go);
        cp16(o + S_BH + 16, bgh + go + 8);
        cp16(o + S_BL,      bgl + go);
        cp16(o + S_BL + 16, bgl + go + 8);
        asm volatile("cp.async.commit_group;" ::: "memory");
    };

    float acc[2][8][4] = {};

    const int NCk = K >> 5;
    issue(0);
    if (NCk > 1) issue(1);

    const int a_row = wm * 32 + (l & 15);
    const int a_kb = ((l >> 4) << 3) * 2;
    const int b_n = wn * 64 + ((l >> 4) << 3) + (l & 7);
    const int b_kb = (((l >> 3) & 1) << 3) * 2;

    for (int c = 0; c < NCk; c++) {
        if (c + 1 < NCk) {
            asm volatile("cp.async.wait_group 1;" ::: "memory");
        } else {
            asm volatile("cp.async.wait_group 0;" ::: "memory");
        }
        __syncthreads();
        if (c + 2 < NCk) issue(c + 2);

        const uint32_t o = sb + (c % 3) * S_BUF;
#pragma unroll
        for (int ks = 0; ks < 2; ks++) {
            const uint32_t kofs = ks * 32 + a_kb;
            uint32_t ah[2][4], al_[2][4];
#pragma unroll
            for (int mi = 0; mi < 2; mi++) {
                ldsm4(ah[mi],  o + S_AH + (a_row + mi * 16) * 80 + kofs);
                ldsm4(al_[mi], o + S_AL + (a_row + mi * 16) * 80 + kofs);
            }
            const uint32_t bkofs = ks * 32 + b_kb;
            uint32_t bh[8][2], bl[8][2];
#pragma unroll
            for (int nj = 0; nj < 8; nj += 2) {
                uint32_t t4[4];
                ldsm4(t4, o + S_BH + (b_n + nj * 8) * 80 + bkofs);
                bh[nj][0] = t4[0]; bh[nj][1] = t4[1];
                bh[nj + 1][0] = t4[2]; bh[nj + 1][1] = t4[3];
                ldsm4(t4, o + S_BL + (b_n + nj * 8) * 80 + bkofs);
                bl[nj][0] = t4[0]; bl[nj][1] = t4[1];
                bl[nj + 1][0] = t4[2]; bl[nj + 1][1] = t4[3];
            }
#pragma unroll
            for (int mi = 0; mi < 2; mi++)
#pragma unroll
                for (int ni = 0; ni < 8; ni++) {
                    mma16816(acc[mi][ni], ah[mi], bh[ni]);
                    mma16816(acc[mi][ni], ah[mi], bl[ni]);
                    mma16816(acc[mi][ni], al_[mi], bh[ni]);
                }
        }
        __syncthreads();
    }

    const int gid = l >> 2, tig = l & 3;
#pragma unroll
    for (int mi = 0; mi < 2; mi++) {
        const int row0 = m0 + wm * 32 + mi * 16 + gid;
#pragma unroll
        for (int ni = 0; ni < 8; ni++) {
            const int col = n0 + wn * 64 + ni * 8 + tig * 2;
            float b0 = bias[col], b1 = bias[col + 1];
            float v0 = acc[mi][ni][0] + b0;
            float v1 = acc[mi][ni][1] + b1;
            float v2 = acc[mi][ni][2] + b0;
            float v3 = acc[mi][ni][3] + b1;
            if (relu) {
                v0 = fmaxf(v0, 0.0f); v1 = fmaxf(v1, 0.0f);
                v2 = fmaxf(v2, 0.0f); v3 = fmaxf(v3, 0.0f);
            }
            if (outmode == 0) {
                float2 p0 = {v0, v1}, p1 = {v2, v3};
                *(float2*)(C + (size_t)row0 * N + col) = p0;
                *(float2*)(C + (size_t)(row0 + 8) * N + col) = p1;
            } else {
                __nv_bfloat162 h0 = __floats2bfloat162_rn(v0, v1);
                float2 f0 = __bfloat1622float2(h0);
                __nv_bfloat162 l0 = __floats2bfloat162_rn(v0 - f0.x, v1 - f0.y);
                __nv_bfloat162 h1 = __floats2bfloat162_rn(v2, v3);
                float2 f1 = __bfloat1622float2(h1);
                __nv_bfloat162 l1 = __floats2bfloat162_rn(v2 - f1.x, v3 - f1.y);
                *(__nv_bfloat162*)(Hout + (size_t)row0 * N + col) = h0;
                *(__nv_bfloat162*)(Lout + (size_t)row0 * N + col) = l0;
                *(__nv_bfloat162*)(Hout + (size_t)(row0 + 8) * N + col) = h1;
                *(__nv_bfloat162*)(Lout + (size_t)(row0 + 8) * N + col) = l1;
            }
        }
    }
}

// ---------------- embedding + PE, fused bf16 split ---------------------------
__global__ __launch_bounds__(256)
void embed_kernel(const int* __restrict__ src,
                  const float* __restrict__ emb,
                  const float* __restrict__ pe,
                  float* __restrict__ x,
                  __nv_bfloat16* __restrict__ H,
                  __nv_bfloat16* __restrict__ L) {
    int row = blockIdx.x;
    int s = row & (SEQ - 1);
    int tok = src[row];
    int c = threadIdx.x * 4;
    const float* erow = emb + (size_t)tok * D_MODEL;
    const float* prow = pe + (size_t)s * D_MODEL;
    float4 e = *(const float4*)(erow + c);
    float4 p = *(const float4*)(prow + c);
    float4 v;
    v.x = e.x * 32.0f + p.x; v.y = e.y * 32.0f + p.y;
    v.z = e.z * 32.0f + p.z; v.w = e.w * 32.0f + p.w;
    size_t idx = (size_t)row * D_MODEL + c;
    *(float4*)(x + idx) = v;
    store_split4(H, L, idx, v);
}

// ---------------- flash-style tiled attention --------------------------------
// Q/K/V packed in one [ROWS, 3072] tensor; writes bf16 hi/lo (O-proj input).
#define ATT_STRIDE 68
#define QKV_STRIDE 3072
#define ATT_SMEM_BYTES ((4 * 64 * ATT_STRIDE) * 4 + 256)

__global__ __launch_bounds__(256, 2)
void attn_tile_kernel(const float* __restrict__ QKV,
                      const int* __restrict__ mask,
                      __nv_bfloat16* __restrict__ Hh,
                      __nv_bfloat16* __restrict__ Ll) {
    extern __shared__ float shm[];
    float* Qs = shm;                            // [64][68]
    float* Ks = shm + 64 * ATT_STRIDE;
    float* Ps = shm + 2 * 64 * ATT_STRIDE;
    float* Vs = shm + 3 * 64 * ATT_STRIDE;
    int*   ms = (int*)(shm + 4 * 64 * ATT_STRIDE);

    const int tid = threadIdx.x;
    const int g = tid & 7;
    const int qp = tid >> 3;                    // 0..31
    const int qt = blockIdx.x, h = blockIdx.y, b = blockIdx.z;

    const int lrow = tid >> 2, lcol = (tid & 3) * 16;
    const float* Qg = QKV + ((size_t)(b * SEQ + qt * 64)) * QKV_STRIDE + h * D_K;
    const float* Kg = QKV + ((size_t)(b * SEQ)) * QKV_STRIDE + 1024 + h * D_K;
    const float* Vg = QKV + ((size_t)(b * SEQ)) * QKV_STRIDE + 2048 + h * D_K;

#pragma unroll
    for (int c = 0; c < 16; c += 4)
        *(float4*)&Qs[lrow * ATT_STRIDE + lcol + c] =
            *(const float4*)(Qg + (size_t)lrow * QKV_STRIDE + lcol + c);

    float m0 = -1e30f, m1 = -1e30f, l0 = 0.0f, l1 = 0.0f;
    float O0[8] = {0}, O1[8] = {0};

    for (int kt = 0; kt < SEQ / 64; kt++) {
        __syncthreads();
#pragma unroll
        for (int c = 0; c < 16; c += 4) {
            *(float4*)&Ks[lrow * ATT_STRIDE + lcol + c] =
                *(const float4*)(Kg + (size_t)(kt * 64 + lrow) * QKV_STRIDE + lcol + c);
            *(float4*)&Vs[lrow * ATT_STRIDE + lcol + c] =
                *(const float4*)(Vg + (size_t)(kt * 64 + lrow) * QKV_STRIDE + lcol + c);
        }
        if (tid < 64) ms[tid] = mask[b * SEQ + kt * 64 + tid];
        __syncthreads();

        float s0[8] = {0}, s1[8] = {0};
#pragma unroll
        for (int d = 0; d < 64; d += 4) {
            float4 qa = *(const float4*)&Qs[qp * ATT_STRIDE + d];
            float4 qb = *(const float4*)&Qs[(qp + 32) * ATT_STRIDE + d];
#pragma unroll
            for (int jj = 0; jj < 8; jj++) {
                float4 kv = *(const float4*)&Ks[(g + 8 * jj) * ATT_STRIDE + d];
                s0[jj] = fmaf(qa.x, kv.x, fmaf(qa.y, kv.y,
                          fmaf(qa.z, kv.z, fmaf(qa.w, kv.w, s0[jj]))));
                s1[jj] = fmaf(qb.x, kv.x, fmaf(qb.y, kv.y,
                          fmaf(qb.z, kv.z, fmaf(qb.w, kv.w, s1[jj]))));
            }
        }

        float tm0 = -1e30f, tm1 = -1e30f;
#pragma unroll
        for (int jj = 0; jj < 8; jj++) {
            int msk = ms[g + 8 * jj];
            float a0 = msk ? s0[jj] * 0.125f : -1e9f;
            float a1 = msk ? s1[jj] * 0.125f : -1e9f;
            s0[jj] = a0; s1[jj] = a1;
            tm0 = fmaxf(tm0, a0); tm1 = fmaxf(tm1, a1);
        }
#pragma unroll
        for (int o = 1; o < 8; o <<= 1) {
            tm0 = fmaxf(tm0, __shfl_xor_sync(0xffffffffu, tm0, o));
            tm1 = fmaxf(tm1, __shfl_xor_sync(0xffffffffu, tm1, o));
        }
        float mn0 = fmaxf(m0, tm0), mn1 = fmaxf(m1, tm1);
        float sc0 = __expf(m0 - mn0), sc1 = __expf(m1 - mn1);
        m0 = mn0; m1 = mn1;

        float ps0 = 0.0f, ps1 = 0.0f;
#pragma unroll
        for (int jj = 0; jj < 8; jj++) {
            float p0 = __expf(s0[jj] - mn0);
            float p1 = __expf(s1[jj] - mn1);
            ps0 += p0; ps1 += p1;
            Ps[qp * ATT_STRIDE + g + 8 * jj] = p0;
            Ps[(qp + 32) * ATT_STRIDE + g + 8 * jj] = p1;
        }
#pragma unroll
        for (int o = 1; o < 8; o <<= 1) {
            ps0 += __shfl_xor_sync(0xffffffffu, ps0, o);
            ps1 += __shfl_xor_sync(0xffffffffu, ps1, o);
        }
        l0 = l0 * sc0 + ps0;
        l1 = l1 * sc1 + ps1;
#pragma unroll
        for (int c = 0; c < 8; c++) { O0[c] *= sc0; O1[c] *= sc1; }
        __syncwarp();

#pragma unroll 4
        for (int j = 0; j < 64; j++) {
            float p0 = Ps[qp * ATT_STRIDE + j];
            float p1 = Ps[(qp + 32) * ATT_STRIDE + j];
            float4 va = *(const float4*)&Vs[j * ATT_STRIDE + 4 * g];
            float4 vb = *(const float4*)&Vs[j * ATT_STRIDE + 32 + 4 * g];
            O0[0] = fmaf(p0, va.x, O0[0]); O0[1] = fmaf(p0, va.y, O0[1]);
            O0[2] = fmaf(p0, va.z, O0[2]); O0[3] = fmaf(p0, va.w, O0[3]);
            O0[4] = fmaf(p0, vb.x, O0[4]); O0[5] = fmaf(p0, vb.y, O0[5]);
            O0[6] = fmaf(p0, vb.z, O0[6]); O0[7] = fmaf(p0, vb.w, O0[7]);
            O1[0] = fmaf(p1, va.x, O1[0]); O1[1] = fmaf(p1, va.y, O1[1]);
            O1[2] = fmaf(p1, va.z, O1[2]); O1[3] = fmaf(p1, va.w, O1[3]);
            O1[4] = fmaf(p1, vb.x, O1[4]); O1[5] = fmaf(p1, vb.y, O1[5]);
            O1[6] = fmaf(p1, vb.z, O1[6]); O1[7] = fmaf(p1, vb.w, O1[7]);
        }
    }

    const float inv0 = 1.0f / l0, inv1 = 1.0f / l1;
    size_t r0 = (size_t)(b * SEQ + qt * 64 + qp) * D_MODEL + h * D_K;
    size_t r1 = (size_t)(b * SEQ + qt * 64 + qp + 32) * D_MODEL + h * D_K;
    float4 w;
    w.x = O0[0] * inv0; w.y = O0[1] * inv0; w.z = O0[2] * inv0; w.w = O0[3] * inv0;
    store_split4(Hh, Ll, r0 + 4 * g, w);
    w.x = O0[4] * inv0; w.y = O0[5] * inv0; w.z = O0[6] * inv0; w.w = O0[7] * inv0;
    store_split4(Hh, Ll, r0 + 32 + 4 * g, w);
    w.x = O1[0] * inv1; w.y = O1[1] * inv1; w.z = O1[2] * inv1; w.w = O1[3] * inv1;
    store_split4(Hh, Ll, r1 + 4 * g, w);
    w.x = O1[4] * inv1; w.y = O1[5] * inv1; w.z = O1[6] * inv1; w.w = O1[7] * inv1;
    store_split4(Hh, Ll, r1 + 32 + 4 * g, w);
}

// ---------------- fused residual add + LayerNorm + optional bf16 split ------
__global__ __launch_bounds__(256)
void add_ln_kernel(const float* __restrict__ x,
                   const float* __restrict__ r,
                   const float* __restrict__ g,
                   const float* __restrict__ bta,
                   float* __restrict__ y,
                   __nv_bfloat16* __restrict__ H,
                   __nv_bfloat16* __restrict__ L,
                   int write_split) {
    const int row = blockIdx.x;
    const int tid = threadIdx.x;
    const int c = tid * 4;
    const size_t idx = (size_t)row * D_MODEL + c;

    float4 xv = *(const float4*)(x + idx);
    float4 rv = *(const float4*)(r + idx);
    float4 v;
    v.x = xv.x + rv.x; v.y = xv.y + rv.y;
    v.z = xv.z + rv.z; v.w = xv.w + rv.w;

    float s = v.x + v.y + v.z + v.w;
    float ss = fmaf(v.x, v.x, fmaf(v.y, v.y, fmaf(v.z, v.z, v.w * v.w)));

    __shared__ float rs[256], rss[256];
    rs[tid] = s; rss[tid] = ss;
    __syncthreads();
    for (int off = 128; off > 0; off >>= 1) {
        if (tid < off) { rs[tid] += rs[tid + off]; rss[tid] += rss[tid + off]; }
        __syncthreads();
    }
    float mean = rs[0] * (1.0f / D_MODEL);
    float var = rss[0] * (1.0f / D_MODEL) - mean * mean;
    float inv = rsqrtf(var + 1e-5f);

    float4 gg = *(const float4*)(g + c);
    float4 bb = *(const float4*)(bta + c);
    float4 o;
    o.x = (v.x - mean) * inv * gg.x + bb.x;
    o.y = (v.y - mean) * inv * gg.y + bb.y;
    o.z = (v.z - mean) * inv * gg.z + bb.z;
    o.w = (v.w - mean) * inv * gg.w + bb.w;
    *(float4*)(y + idx) = o;
    if (write_split) store_split4(H, L, idx, o);
}

// ---------------- host orchestration ---------------------------------------
extern "C" void kernel_launch(void* const* d_in, const int* in_sizes, int n_in,
                              void* d_out, int out_size) {
    const int*   src  = (const int*)d_in[0];
    const int*   mask = (const int*)d_in[1];
    const float* emb  = (const float*)d_in[2];
    const float* pe   = (const float*)d_in[3];
    const float* wq = (const float*)d_in[4];
    const float* bq = (const float*)d_in[5];
    const float* wk = (const float*)d_in[6];
    const float* bk = (const float*)d_in[7];
    const float* wv = (const float*)d_in[8];
    const float* bv = (const float*)d_in[9];
    const float* wo = (const float*)d_in[10];
    const float* bo = (const float*)d_in[11];
    const float* w1 = (const float*)d_in[12];
    const float* b1 = (const float*)d_in[13];
    const float* w2 = (const float*)d_in[14];
    const float* b2 = (const float*)d_in[15];
    const float* g1  = (const float*)d_in[16];
    const float* be1 = (const float*)d_in[17];
    const float* g2  = (const float*)d_in[18];
    const float* be2 = (const float*)d_in[19];
    float* out = (float*)d_out;

    float *px, *pqkv, *pt, *pbqkv;
    cudaGetSymbolAddress((void**)&px, g_x);
    cudaGetSymbolAddress((void**)&pqkv, g_qkv);
    cudaGetSymbolAddress((void**)&pt, g_t);
    cudaGetSymbolAddress((void**)&pbqkv, g_bqkv);

    __nv_bfloat16 *ah, *al, *hh, *hl;
    cudaGetSymbolAddress((void**)&ah, g_ah);
    cudaGetSymbolAddress((void**)&al, g_al);
    cudaGetSymbolAddress((void**)&hh, g_hh);
    cudaGetSymbolAddress((void**)&hl, g_hl);

    __nv_bfloat16 *wqkvt_h, *wqkvt_l, *wot_h, *wot_l;
    __nv_bfloat16 *w1t_h, *w1t_l, *w2t_h, *w2t_l;
    cudaGetSymbolAddress((void**)&wqkvt_h, g_wqkvt_h);
    cudaGetSymbolAddress((void**)&wqkvt_l, g_wqkvt_l);
    cudaGetSymbolAddress((void**)&wot_h, g_wot_h);
    cudaGetSymbolAddress((void**)&wot_l, g_wot_l);
    cudaGetSymbolAddress((void**)&w1t_h, g_w1t_h);
    cudaGetSymbolAddress((void**)&w1t_l, g_w1t_l);
    cudaGetSymbolAddress((void**)&w2t_h, g_w2t_h);
    cudaGetSymbolAddress((void**)&w2t_l, g_w2t_l);

    static int attr_set = 0;
    if (!attr_set) {
        cudaFuncSetAttribute(gemm_tc, cudaFuncAttributeMaxDynamicSharedMemorySize,
                             GEMM_SMEM_BYTES);
        cudaFuncSetAttribute(attn_tile_kernel,
                             cudaFuncAttributeMaxDynamicSharedMemorySize,
                             ATT_SMEM_BYTES);
        attr_set = 1;
    }

    // ---- weight prep ----
    dim3 tblk(32, 8);
    const size_t qkv_ls = (size_t)3072 * 1024;
    transpose_split_kernel<<<dim3(32, 32, 6), tblk>>>(wq, wqkvt_h, wqkvt_l,
                                                      1024, 1024, qkv_ls, 0);
    transpose_split_kernel<<<dim3(32, 32, 6), tblk>>>(wk, wqkvt_h, wqkvt_l,
                                                      1024, 1024, qkv_ls, 1024);
    transpose_split_kernel<<<dim3(32, 32, 6), tblk>>>(wv, wqkvt_h, wqkvt_l,
                                                      1024, 1024, qkv_ls, 2048);
    transpose_split_kernel<<<dim3(32, 32, 6), tblk>>>(wo, wot_h, wot_l,
                                                      1024, 1024, (size_t)1024 * 1024, 0);
    transpose_split_kernel<<<dim3(128, 32, 6), tblk>>>(w1, w1t_h, w1t_l,
                                                       1024, 4096, (size_t)4096 * 1024, 0);
    transpose_split_kernel<<<dim3(32, 128, 6), tblk>>>(w2, w2t_h, w2t_l,
                                                       4096, 1024, (size_t)4096 * 1024, 0);
    concat_bias_kernel<<<dim3(12, 6), 256>>>(bq, bk, bv, pbqkv);

    embed_kernel<<<ROWS, 256>>>(src, emb, pe, px, ah, al);

    dim3 g_qkv_grid(3072 / 128, ROWS / 128);   // (24, 32)
    dim3 g_dd(D_MODEL / 128, ROWS / 128);      // (8, 32)
    dim3 g_ff(D_FF / 128,    ROWS / 128);      // (32, 32)
    dim3 attn_grid(SEQ / 64, N_HEADS, BATCH);

    for (int l = 0; l < N_LAYERS; l++) {
        size_t woqkv = (size_t)l * 3072 * 1024;
        size_t wofs  = (size_t)l * 1024 * 1024;
        size_t bofs  = (size_t)l * D_MODEL;
        size_t wfofs = (size_t)l * 4096 * 1024;
        size_t b1ofs = (size_t)l * D_FF;

        // fused QKV projection: [4096,3072] = A[4096,1024] @ Wqkv^T
        gemm_tc<<<g_qkv_grid, 256, GEMM_SMEM_BYTES>>>(
            ah, al, wqkvt_h + woqkv, wqkvt_l + woqkv, pbqkv + l * 3072,
            pqkv, nullptr, nullptr, ROWS, 3072, 1024, 0, 0);

        // attention -> bf16 split (O-proj input), overwrites ah/al
        attn_tile_kernel<<<attn_grid, 256, ATT_SMEM_BYTES>>>(pqkv, mask, ah, al);

        // O projection -> fp32 g_t
        gemm_tc<<<g_dd, 256, GEMM_SMEM_BYTES>>>(
            ah, al, wot_h + wofs, wot_l + wofs, bo + bofs,
            pt, nullptr, nullptr, ROWS, 1024, 1024, 0, 0);

        // add + LN #1 -> px fp32 + bf16 split (FFN1 input)
        add_ln_kernel<<<ROWS, 256>>>(px, pt, g1 + bofs, be1 + bofs, px, ah, al, 1);

        // FFN1 (relu) -> bf16 split directly (FFN2 input)
        gemm_tc<<<g_ff, 256, GEMM_SMEM_BYTES>>>(
            ah, al, w1t_h + wfofs, w1t_l + wfofs, b1 + b1ofs,
            nullptr, hh, hl, ROWS, 4096, 1024, 1, 1);

        // FFN2 -> fp32 g_t
        gemm_tc<<<g_dd, 256, GEMM_SMEM_BYTES>>>(
            hh, hl, w2t_h + wfofs, w2t_l + wfofs, b2 + bofs,
            pt, nullptr, nullptr, ROWS, 1024, 4096, 0, 0);

        // add + LN #2 -> (last layer: d_out, no split) else px + split
        if (l == N_LAYERS - 1) {
            add_ln_kernel<<<ROWS, 256>>>(px, pt, g2 + bofs, be2 + bofs, out,
                                         ah, al, 0);
        } else {
            add_ln_kernel<<<ROWS, 256>>>(px, pt, g2 + bofs, be2 + bofs, px,
                                         ah, al, 1);
        }
    }
}

// round 8
// speedup vs baseline: 4.0770x; 1.0921x over previous
#include <cuda_runtime.h>
#include <cuda_bf16.h>
#include <math.h>
#include <stdint.h>

#define D_MODEL 1024
#define N_HEADS 16
#define D_K 64
#define D_FF 4096
#define N_LAYERS 6
#define BATCH 4
#define SEQ 1024
#define ROWS (BATCH * SEQ)   // 4096

// ---------------- scratch (device globals; no allocation allowed) ----------
__device__ float g_x[ROWS * D_MODEL];                 // residual stream (fp32)
__device__ float g_qkv[(size_t)ROWS * 3 * D_MODEL];   // fused QKV output
__device__ float g_t[ROWS * D_MODEL];                 // pre-LN gemm output
__device__ __nv_bfloat16 g_ah[(size_t)ROWS * D_MODEL];  // activation hi
__device__ __nv_bfloat16 g_al[(size_t)ROWS * D_MODEL];  // activation lo
__device__ __nv_bfloat16 g_hh[(size_t)ROWS * D_FF];     // ffn hidden hi
__device__ __nv_bfloat16 g_hl[(size_t)ROWS * D_FF];     // ffn hidden lo

// transposed + split weights: [N,K] K-major bf16, hi and lo parts
__device__ __nv_bfloat16 g_wqkvt_h[6u*3072*1024], g_wqkvt_l[6u*3072*1024];
__device__ __nv_bfloat16 g_wot_h[6u*1024*1024],  g_wot_l[6u*1024*1024];
__device__ __nv_bfloat16 g_w1t_h[6u*4096*1024],  g_w1t_l[6u*4096*1024];
__device__ __nv_bfloat16 g_w2t_h[6u*4096*1024],  g_w2t_l[6u*4096*1024];
__device__ float g_bqkv[6 * 3072];

// ---------------- PTX helpers ------------------------------------------------
__device__ __forceinline__ uint32_t smem_u32(const void* p) {
    uint32_t a;
    asm("{ .reg .u64 t; cvta.to.shared.u64 t, %1; cvt.u32.u64 %0, t; }"
        : "=r"(a) : "l"(p));
    return a;
}

__device__ __forceinline__ void cp16(uint32_t s, const void* g) {
    asm volatile("cp.async.cg.shared.global [%0], [%1], 16;"
                 :: "r"(s), "l"(g) : "memory");
}

__device__ __forceinline__ void ldsm4(uint32_t* r, uint32_t addr) {
    asm volatile("ldmatrix.sync.aligned.m8n8.x4.shared.b16 {%0,%1,%2,%3}, [%4];"
                 : "=r"(r[0]), "=r"(r[1]), "=r"(r[2]), "=r"(r[3]) : "r"(addr));
}

__device__ __forceinline__ void mma16816(float* c, const uint32_t* a,
                                         const uint32_t* b) {
    asm volatile(
        "mma.sync.aligned.m16n8k16.row.col.f32.bf16.bf16.f32 "
        "{%0,%1,%2,%3}, {%4,%5,%6,%7}, {%8,%9}, {%0,%1,%2,%3};"
        : "+f"(c[0]), "+f"(c[1]), "+f"(c[2]), "+f"(c[3])
        : "r"(a[0]), "r"(a[1]), "r"(a[2]), "r"(a[3]), "r"(b[0]), "r"(b[1]));
}

// split a float4 into bf16 hi/lo pairs, store 8B each
__device__ __forceinline__ void store_split4(__nv_bfloat16* H, __nv_bfloat16* L,
                                             size_t idx, float4 v) {
    __nv_bfloat162 h0 = __floats2bfloat162_rn(v.x, v.y);
    __nv_bfloat162 h1 = __floats2bfloat162_rn(v.z, v.w);
    float2 f0 = __bfloat1622float2(h0);
    float2 f1 = __bfloat1622float2(h1);
    __nv_bfloat162 l0 = __floats2bfloat162_rn(v.x - f0.x, v.y - f0.y);
    __nv_bfloat162 l1 = __floats2bfloat162_rn(v.z - f1.x, v.w - f1.y);
    uint2 hh, ll;
    hh.x = *reinterpret_cast<uint32_t*>(&h0);
    hh.y = *reinterpret_cast<uint32_t*>(&h1);
    ll.x = *reinterpret_cast<uint32_t*>(&l0);
    ll.y = *reinterpret_cast<uint32_t*>(&l1);
    *(uint2*)(H + idx) = hh;
    *(uint2*)(L + idx) = ll;
}

// ---------------- weight transpose + bf16 hi/lo split -----------------------
__global__ void transpose_split_kernel(const float* __restrict__ W,
                                       __nv_bfloat16* __restrict__ Th,
                                       __nv_bfloat16* __restrict__ Tl,
                                       int K, int N, size_t out_lstride,
                                       int row_off) {
    __shared__ float t[32][33];
    const float* Wl = W + (size_t)blockIdx.z * K * N;
    int n0 = blockIdx.x * 32, k0 = blockIdx.y * 32;
    int tx = threadIdx.x, ty = threadIdx.y;
#pragma unroll
    for (int i = ty; i < 32; i += 8)
        t[i][tx] = Wl[(size_t)(k0 + i) * N + n0 + tx];
    __syncthreads();
#pragma unroll
    for (int i = ty; i < 32; i += 8) {
        float v = t[tx][i];
        __nv_bfloat16 h = __float2bfloat16(v);
        float lo = v - __bfloat162float(h);
        size_t o = (size_t)blockIdx.z * out_lstride +
                   (size_t)(row_off + n0 + i) * K + k0 + tx;
        Th[o] = h;
        Tl[o] = __float2bfloat16(lo);
    }
}

__global__ void concat_bias_kernel(const float* __restrict__ bq,
                                   const float* __restrict__ bk,
                                   const float* __restrict__ bv,
                                   float* __restrict__ dst) {
    int l = blockIdx.y;
    int i = blockIdx.x * 256 + threadIdx.x;   // 0..3071
    float v;
    if (i < 1024) v = bq[l * 1024 + i];
    else if (i < 2048) v = bk[l * 1024 + i - 1024];
    else v = bv[l * 1024 + i - 2048];
    dst[l * 3072 + i] = v;
}

// ---------------- mma.sync bf16 split-3 GEMM --------------------------------
// C[M,N] = A[M,K] @ B[N,K]^T + bias. 2-stage cp.async pipeline, 2 CTAs/SM.
// outmode 0: fp32 -> C;  outmode 1: bf16 hi/lo -> Hout/Lout.
#define S_AH 0
#define S_AL 10240
#define S_BH 20480
#define S_BL 30720
#define S_BUF 40960
#define GEMM_SMEM_BYTES (2 * S_BUF)   // 81920

__global__ __launch_bounds__(256, 2)
void gemm_tc(const __nv_bfloat16* __restrict__ Ah,
             const __nv_bfloat16* __restrict__ Al,
             const __nv_bfloat16* __restrict__ Bh,
             const __nv_bfloat16* __restrict__ Bl,
             const float* __restrict__ bias,
             float* __restrict__ C,
             __nv_bfloat16* __restrict__ Hout,
             __nv_bfloat16* __restrict__ Lout,
             int M, int N, int K, int relu, int outmode) {
    extern __shared__ char sm[];
    const uint32_t sb = smem_u32(sm);

    const int tid = threadIdx.x;
    const int l = tid & 31, w = tid >> 5;
    const int wm = w & 3, wn = w >> 2;
    const int m0 = blockIdx.y * 128, n0 = blockIdx.x * 128;

    const int lr = tid >> 1;
    const int lkc = (tid & 1) * 2;

    const __nv_bfloat16* agh = Ah + (size_t)(m0 + lr) * K + lkc * 8;
    const __nv_bfloat16* agl = Al + (size_t)(m0 + lr) * K + lkc * 8;
    const __nv_bfloat16* bgh = Bh + (size_t)(n0 + lr) * K + lkc * 8;
    const __nv_bfloat16* bgl = Bl + (size_t)(n0 + lr) * K + lkc * 8;
    const uint32_t srow = lr * 80 + lkc * 16;

    auto issue = [&](int c) {
        const uint32_t o = sb + (c & 1) * S_BUF + srow;
        const size_t go = (size_t)c * 32;
        cp16(o + S_AH,      agh + go);
        cp16(o + S_AH + 16, agh + go + 8);
        cp16(o + S_AL,      agl + go);
        cp16(o + S_AL + 16, agl + go + 8);
        cp16(o + S_BH,      bgh + go);
        cp16(o + S_BH + 16, bgh + go + 8);
        cp16(o + S_BL,      bgl + go);
        cp16(o + S_BL + 16, bgl + go + 8);
        asm volatile("cp.async.commit_group;" ::: "memory");
    };

    float acc[2][8][4] = {};

    const int NCk = K >> 5;
    issue(0);

    const int a_row = wm * 32 + (l & 15);
    const int a_kb = ((l >> 4) << 3) * 2;
    const int b_n = wn * 64 + ((l >> 4) << 3) + (l & 7);
    const int b_kb = (((l >> 3) & 1) << 3) * 2;

    for (int c = 0; c < NCk; c++) {
        if (c + 1 < NCk) {
            issue(c + 1);   // buffer (c+1)&1 freed by sync at end of iter c-1
            asm volatile("cp.async.wait_group 1;" ::: "memory");
        } else {
            asm volatile("cp.async.wait_group 0;" ::: "memory");
        }
        __syncthreads();

        const uint32_t o = sb + (c & 1) * S_BUF;
#pragma unroll
        for (int ks = 0; ks < 2; ks++) {
            const uint32_t kofs = ks * 32 + a_kb;
            uint32_t ah[2][4], al_[2][4];
#pragma unroll
            for (int mi = 0; mi < 2; mi++) {
                ldsm4(ah[mi],  o + S_AH + (a_row + mi * 16) * 80 + kofs);
                ldsm4(al_[mi], o + S_AL + (a_row + mi * 16) * 80 + kofs);
            }
            const uint32_t bkofs = ks * 32 + b_kb;
            // process B in nj-pairs to keep register pressure low (2 CTAs/SM)
#pragma unroll
            for (int nj = 0; nj < 8; nj += 2) {
                uint32_t bh2[4], bl2[4];
                ldsm4(bh2, o + S_BH + (b_n + nj * 8) * 80 + bkofs);
                ldsm4(bl2, o + S_BL + (b_n + nj * 8) * 80 + bkofs);
#pragma unroll
                for (int mi = 0; mi < 2; mi++) {
                    mma16816(acc[mi][nj],     ah[mi],  bh2);
                    mma16816(acc[mi][nj + 1], ah[mi],  bh2 + 2);
                    mma16816(acc[mi][nj],     ah[mi],  bl2);
                    mma16816(acc[mi][nj + 1], ah[mi],  bl2 + 2);
                    mma16816(acc[mi][nj],     al_[mi], bh2);
                    mma16816(acc[mi][nj + 1], al_[mi], bh2 + 2);
                }
            }
        }
        __syncthreads();
    }

    const int gid = l >> 2, tig = l & 3;
#pragma unroll
    for (int mi = 0; mi < 2; mi++) {
        const int row0 = m0 + wm * 32 + mi * 16 + gid;
#pragma unroll
        for (int ni = 0; ni < 8; ni++) {
            const int col = n0 + wn * 64 + ni * 8 + tig * 2;
            float b0 = bias[col], b1 = bias[col + 1];
            float v0 = acc[mi][ni][0] + b0;
            float v1 = acc[mi][ni][1] + b1;
            float v2 = acc[mi][ni][2] + b0;
            float v3 = acc[mi][ni][3] + b1;
            if (relu) {
                v0 = fmaxf(v0, 0.0f); v1 = fmaxf(v1, 0.0f);
                v2 = fmaxf(v2, 0.0f); v3 = fmaxf(v3, 0.0f);
            }
            if (outmode == 0) {
                float2 p0 = {v0, v1}, p1 = {v2, v3};
                *(float2*)(C + (size_t)row0 * N + col) = p0;
                *(float2*)(C + (size_t)(row0 + 8) * N + col) = p1;
            } else {
                __nv_bfloat162 h0 = __floats2bfloat162_rn(v0, v1);
                float2 f0 = __bfloat1622float2(h0);
                __nv_bfloat162 l0 = __floats2bfloat162_rn(v0 - f0.x, v1 - f0.y);
                __nv_bfloat162 h1 = __floats2bfloat162_rn(v2, v3);
                float2 f1 = __bfloat1622float2(h1);
                __nv_bfloat162 l1 = __floats2bfloat162_rn(v2 - f1.x, v3 - f1.y);
                *(__nv_bfloat162*)(Hout + (size_t)row0 * N + col) = h0;
                *(__nv_bfloat162*)(Lout + (size_t)row0 * N + col) = l0;
                *(__nv_bfloat162*)(Hout + (size_t)(row0 + 8) * N + col) = h1;
                *(__nv_bfloat162*)(Lout + (size_t)(row0 + 8) * N + col) = l1;
            }
        }
    }
}

// ---------------- embedding + PE, fused bf16 split ---------------------------
__global__ __launch_bounds__(256)
void embed_kernel(const int* __restrict__ src,
                  const float* __restrict__ emb,
                  const float* __restrict__ pe,
                  float* __restrict__ x,
                  __nv_bfloat16* __restrict__ H,
                  __nv_bfloat16* __restrict__ L) {
    int row = blockIdx.x;
    int s = row & (SEQ - 1);
    int tok = src[row];
    int c = threadIdx.x * 4;
    const float* erow = emb + (size_t)tok * D_MODEL;
    const float* prow = pe + (size_t)s * D_MODEL;
    float4 e = *(const float4*)(erow + c);
    float4 p = *(const float4*)(prow + c);
    float4 v;
    v.x = e.x * 32.0f + p.x; v.y = e.y * 32.0f + p.y;
    v.z = e.z * 32.0f + p.z; v.w = e.w * 32.0f + p.w;
    size_t idx = (size_t)row * D_MODEL + c;
    *(float4*)(x + idx) = v;
    store_split4(H, L, idx, v);
}

// ---------------- flash-style tiled attention --------------------------------
#define ATT_STRIDE 68
#define QKV_STRIDE 3072
#define ATT_SMEM_BYTES ((4 * 64 * ATT_STRIDE) * 4 + 256)

__global__ __launch_bounds__(256, 2)
void attn_tile_kernel(const float* __restrict__ QKV,
                      const int* __restrict__ mask,
                      __nv_bfloat16* __restrict__ Hh,
                      __nv_bfloat16* __restrict__ Ll) {
    extern __shared__ float shm[];
    float* Qs = shm;                            // [64][68]
    float* Ks = shm + 64 * ATT_STRIDE;
    float* Ps = shm + 2 * 64 * ATT_STRIDE;
    float* Vs = shm + 3 * 64 * ATT_STRIDE;
    int*   ms = (int*)(shm + 4 * 64 * ATT_STRIDE);

    const int tid = threadIdx.x;
    const int g = tid & 7;
    const int qp = tid >> 3;                    // 0..31
    const int qt = blockIdx.x, h = blockIdx.y, b = blockIdx.z;

    const int lrow = tid >> 2, lcol = (tid & 3) * 16;
    const float* Qg = QKV + ((size_t)(b * SEQ + qt * 64)) * QKV_STRIDE + h * D_K;
    const float* Kg = QKV + ((size_t)(b * SEQ)) * QKV_STRIDE + 1024 + h * D_K;
    const float* Vg = QKV + ((size_t)(b * SEQ)) * QKV_STRIDE + 2048 + h * D_K;

#pragma unroll
    for (int c = 0; c < 16; c += 4)
        *(float4*)&Qs[lrow * ATT_STRIDE + lcol + c] =
            *(const float4*)(Qg + (size_t)lrow * QKV_STRIDE + lcol + c);

    float m0 = -1e30f, m1 = -1e30f, l0 = 0.0f, l1 = 0.0f;
    float O0[8] = {0}, O1[8] = {0};

    for (int kt = 0; kt < SEQ / 64; kt++) {
        __syncthreads();
#pragma unroll
        for (int c = 0; c < 16; c += 4) {
            *(float4*)&Ks[lrow * ATT_STRIDE + lcol + c] =
                *(const float4*)(Kg + (size_t)(kt * 64 + lrow) * QKV_STRIDE + lcol + c);
            *(float4*)&Vs[lrow * ATT_STRIDE + lcol + c] =
                *(const float4*)(Vg + (size_t)(kt * 64 + lrow) * QKV_STRIDE + lcol + c);
        }
        if (tid < 64) ms[tid] = mask[b * SEQ + kt * 64 + tid];
        __syncthreads();

        float s0[8] = {0}, s1[8] = {0};
#pragma unroll
        for (int d = 0; d < 64; d += 4) {
            float4 qa = *(const float4*)&Qs[qp * ATT_STRIDE + d];
            float4 qb = *(const float4*)&Qs[(qp + 32) * ATT_STRIDE + d];
#pragma unroll
            for (int jj = 0; jj < 8; jj++) {
                float4 kv = *(const float4*)&Ks[(g + 8 * jj) * ATT_STRIDE + d];
                s0[jj] = fmaf(qa.x, kv.x, fmaf(qa.y, kv.y,
                          fmaf(qa.z, kv.z, fmaf(qa.w, kv.w, s0[jj]))));
                s1[jj] = fmaf(qb.x, kv.x, fmaf(qb.y, kv.y,
                          fmaf(qb.z, kv.z, fmaf(qb.w, kv.w, s1[jj]))));
            }
        }

        float tm0 = -1e30f, tm1 = -1e30f;
#pragma unroll
        for (int jj = 0; jj < 8; jj++) {
            int msk = ms[g + 8 * jj];
            float a0 = msk ? s0[jj] * 0.125f : -1e9f;
            float a1 = msk ? s1[jj] * 0.125f : -1e9f;
            s0[jj] = a0; s1[jj] = a1;
            tm0 = fmaxf(tm0, a0); tm1 = fmaxf(tm1, a1);
        }
#pragma unroll
        for (int o = 1; o < 8; o <<= 1) {
            tm0 = fmaxf(tm0, __shfl_xor_sync(0xffffffffu, tm0, o));
            tm1 = fmaxf(tm1, __shfl_xor_sync(0xffffffffu, tm1, o));
        }
        float mn0 = fmaxf(m0, tm0), mn1 = fmaxf(m1, tm1);
        float sc0 = __expf(m0 - mn0), sc1 = __expf(m1 - mn1);
        m0 = mn0; m1 = mn1;

        float ps0 = 0.0f, ps1 = 0.0f;
#pragma unroll
        for (int jj = 0; jj < 8; jj++) {
            float p0 = __expf(s0[jj] - mn0);
            float p1 = __expf(s1[jj] - mn1);
            ps0 += p0; ps1 += p1;
            Ps[qp * ATT_STRIDE + g + 8 * jj] = p0;
            Ps[(qp + 32) * ATT_STRIDE + g + 8 * jj] = p1;
        }
#pragma unroll
        for (int o = 1; o < 8; o <<= 1) {
            ps0 += __shfl_xor_sync(0xffffffffu, ps0, o);
            ps1 += __shfl_xor_sync(0xffffffffu, ps1, o);
        }
        l0 = l0 * sc0 + ps0;
        l1 = l1 * sc1 + ps1;
#pragma unroll
        for (int c = 0; c < 8; c++) { O0[c] *= sc0; O1[c] *= sc1; }
        __syncwarp();

#pragma unroll 4
        for (int j = 0; j < 64; j++) {
            float p0 = Ps[qp * ATT_STRIDE + j];
            float p1 = Ps[(qp + 32) * ATT_STRIDE + j];
            float4 va = *(const float4*)&Vs[j * ATT_STRIDE + 4 * g];
            float4 vb = *(const float4*)&Vs[j * ATT_STRIDE + 32 + 4 * g];
            O0[0] = fmaf(p0, va.x, O0[0]); O0[1] = fmaf(p0, va.y, O0[1]);
            O0[2] = fmaf(p0, va.z, O0[2]); O0[3] = fmaf(p0, va.w, O0[3]);
            O0[4] = fmaf(p0, vb.x, O0[4]); O0[5] = fmaf(p0, vb.y, O0[5]);
            O0[6] = fmaf(p0, vb.z, O0[6]); O0[7] = fmaf(p0, vb.w, O0[7]);
            O1[0] = fmaf(p1, va.x, O1[0]); O1[1] = fmaf(p1, va.y, O1[1]);
            O1[2] = fmaf(p1, va.z, O1[2]); O1[3] = fmaf(p1, va.w, O1[3]);
            O1[4] = fmaf(p1, vb.x, O1[4]); O1[5] = fmaf(p1, vb.y, O1[5]);
            O1[6] = fmaf(p1, vb.z, O1[6]); O1[7] = fmaf(p1, vb.w, O1[7]);
        }
    }

    const float inv0 = 1.0f / l0, inv1 = 1.0f / l1;
    size_t r0 = (size_t)(b * SEQ + qt * 64 + qp) * D_MODEL + h * D_K;
    size_t r1 = (size_t)(b * SEQ + qt * 64 + qp + 32) * D_MODEL + h * D_K;
    float4 w;
    w.x = O0[0] * inv0; w.y = O0[1] * inv0; w.z = O0[2] * inv0; w.w = O0[3] * inv0;
    store_split4(Hh, Ll, r0 + 4 * g, w);
    w.x = O0[4] * inv0; w.y = O0[5] * inv0; w.z = O0[6] * inv0; w.w = O0[7] * inv0;
    store_split4(Hh, Ll, r0 + 32 + 4 * g, w);
    w.x = O1[0] * inv1; w.y = O1[1] * inv1; w.z = O1[2] * inv1; w.w = O1[3] * inv1;
    store_split4(Hh, Ll, r1 + 4 * g, w);
    w.x = O1[4] * inv1; w.y = O1[5] * inv1; w.z = O1[6] * inv1; w.w = O1[7] * inv1;
    store_split4(Hh, Ll, r1 + 32 + 4 * g, w);
}

// ---------------- fused residual add + LayerNorm + optional bf16 split ------
__global__ __launch_bounds__(256)
void add_ln_kernel(const float* __restrict__ x,
                   const float* __restrict__ r,
                   const float* __restrict__ g,
                   const float* __restrict__ bta,
                   float* __restrict__ y,
                   __nv_bfloat16* __restrict__ H,
                   __nv_bfloat16* __restrict__ L,
                   int write_split) {
    const int row = blockIdx.x;
    const int tid = threadIdx.x;
    const int c = tid * 4;
    const size_t idx = (size_t)row * D_MODEL + c;

    float4 xv = *(const float4*)(x + idx);
    float4 rv = *(const float4*)(r + idx);
    float4 v;
    v.x = xv.x + rv.x; v.y = xv.y + rv.y;
    v.z = xv.z + rv.z; v.w = xv.w + rv.w;

    float s = v.x + v.y + v.z + v.w;
    float ss = fmaf(v.x, v.x, fmaf(v.y, v.y, fmaf(v.z, v.z, v.w * v.w)));

    __shared__ float rs[256], rss[256];
    rs[tid] = s; rss[tid] = ss;
    __syncthreads();
    for (int off = 128; off > 0; off >>= 1) {
        if (tid < off) { rs[tid] += rs[tid + off]; rss[tid] += rss[tid + off]; }
        __syncthreads();
    }
    float mean = rs[0] * (1.0f / D_MODEL);
    float var = rss[0] * (1.0f / D_MODEL) - mean * mean;
    float inv = rsqrtf(var + 1e-5f);

    float4 gg = *(const float4*)(g + c);
    float4 bb = *(const float4*)(bta + c);
    float4 o;
    o.x = (v.x - mean) * inv * gg.x + bb.x;
    o.y = (v.y - mean) * inv * gg.y + bb.y;
    o.z = (v.z - mean) * inv * gg.z + bb.z;
    o.w = (v.w - mean) * inv * gg.w + bb.w;
    *(float4*)(y + idx) = o;
    if (write_split) store_split4(H, L, idx, o);
}

// ---------------- host orchestration ---------------------------------------
extern "C" void kernel_launch(void* const* d_in, const int* in_sizes, int n_in,
                              void* d_out, int out_size) {
    const int*   src  = (const int*)d_in[0];
    const int*   mask = (const int*)d_in[1];
    const float* emb  = (const float*)d_in[2];
    const float* pe   = (const float*)d_in[3];
    const float* wq = (const float*)d_in[4];
    const float* bq = (const float*)d_in[5];
    const float* wk = (const float*)d_in[6];
    const float* bk = (const float*)d_in[7];
    const float* wv = (const float*)d_in[8];
    const float* bv = (const float*)d_in[9];
    const float* wo = (const float*)d_in[10];
    const float* bo = (const float*)d_in[11];
    const float* w1 = (const float*)d_in[12];
    const float* b1 = (const float*)d_in[13];
    const float* w2 = (const float*)d_in[14];
    const float* b2 = (const float*)d_in[15];
    const float* g1  = (const float*)d_in[16];
    const float* be1 = (const float*)d_in[17];
    const float* g2  = (const float*)d_in[18];
    const float* be2 = (const float*)d_in[19];
    float* out = (float*)d_out;

    float *px, *pqkv, *pt, *pbqkv;
    cudaGetSymbolAddress((void**)&px, g_x);
    cudaGetSymbolAddress((void**)&pqkv, g_qkv);
    cudaGetSymbolAddress((void**)&pt, g_t);
    cudaGetSymbolAddress((void**)&pbqkv, g_bqkv);

    __nv_bfloat16 *ah, *al, *hh, *hl;
    cudaGetSymbolAddress((void**)&ah, g_ah);
    cudaGetSymbolAddress((void**)&al, g_al);
    cudaGetSymbolAddress((void**)&hh, g_hh);
    cudaGetSymbolAddress((void**)&hl, g_hl);

    __nv_bfloat16 *wqkvt_h, *wqkvt_l, *wot_h, *wot_l;
    __nv_bfloat16 *w1t_h, *w1t_l, *w2t_h, *w2t_l;
    cudaGetSymbolAddress((void**)&wqkvt_h, g_wqkvt_h);
    cudaGetSymbolAddress((void**)&wqkvt_l, g_wqkvt_l);
    cudaGetSymbolAddress((void**)&wot_h, g_wot_h);
    cudaGetSymbolAddress((void**)&wot_l, g_wot_l);
    cudaGetSymbolAddress((void**)&w1t_h, g_w1t_h);
    cudaGetSymbolAddress((void**)&w1t_l, g_w1t_l);
    cudaGetSymbolAddress((void**)&w2t_h, g_w2t_h);
    cudaGetSymbolAddress((void**)&w2t_l, g_w2t_l);

    static int attr_set = 0;
    if (!attr_set) {
        cudaFuncSetAttribute(gemm_tc, cudaFuncAttributeMaxDynamicSharedMemorySize,
                             GEMM_SMEM_BYTES);
        cudaFuncSetAttribute(attn_tile_kernel,
                             cudaFuncAttributeMaxDynamicSharedMemorySize,
                             ATT_SMEM_BYTES);
        attr_set = 1;
    }

    // ---- weight prep ----
    dim3 tblk(32, 8);
    const size_t qkv_ls = (size_t)3072 * 1024;
    transpose_split_kernel<<<dim3(32, 32, 6), tblk>>>(wq, wqkvt_h, wqkvt_l,
                                                      1024, 1024, qkv_ls, 0);
    transpose_split_kernel<<<dim3(32, 32, 6), tblk>>>(wk, wqkvt_h, wqkvt_l,
                                                      1024, 1024, qkv_ls, 1024);
    transpose_split_kernel<<<dim3(32, 32, 6), tblk>>>(wv, wqkvt_h, wqkvt_l,
                                                      1024, 1024, qkv_ls, 2048);
    transpose_split_kernel<<<dim3(32, 32, 6), tblk>>>(wo, wot_h, wot_l,
                                                      1024, 1024, (size_t)1024 * 1024, 0);
    transpose_split_kernel<<<dim3(128, 32, 6), tblk>>>(w1, w1t_h, w1t_l,
                                                       1024, 4096, (size_t)4096 * 1024, 0);
    transpose_split_kernel<<<dim3(32, 128, 6), tblk>>>(w2, w2t_h, w2t_l,
                                                       4096, 1024, (size_t)4096 * 1024, 0);
    concat_bias_kernel<<<dim3(12, 6), 256>>>(bq, bk, bv, pbqkv);

    embed_kernel<<<ROWS, 256>>>(src, emb, pe, px, ah, al);

    dim3 g_qkv_grid(3072 / 128, ROWS / 128);   // (24, 32)
    dim3 g_dd(D_MODEL / 128, ROWS / 128);      // (8, 32)
    dim3 g_ff(D_FF / 128,    ROWS / 128);      // (32, 32)
    dim3 attn_grid(SEQ / 64, N_HEADS, BATCH);

    for (int l = 0; l < N_LAYERS; l++) {
        size_t woqkv = (size_t)l * 3072 * 1024;
        size_t wofs  = (size_t)l * 1024 * 1024;
        size_t bofs  = (size_t)l * D_MODEL;
        size_t wfofs = (size_t)l * 4096 * 1024;
        size_t b1ofs = (size_t)l * D_FF;

        gemm_tc<<<g_qkv_grid, 256, GEMM_SMEM_BYTES>>>(
            ah, al, wqkvt_h + woqkv, wqkvt_l + woqkv, pbqkv + l * 3072,
            pqkv, nullptr, nullptr, ROWS, 3072, 1024, 0, 0);

        attn_tile_kernel<<<attn_grid, 256, ATT_SMEM_BYTES>>>(pqkv, mask, ah, al);

        gemm_tc<<<g_dd, 256, GEMM_SMEM_BYTES>>>(
            ah, al, wot_h + wofs, wot_l + wofs, bo + bofs,
            pt, nullptr, nullptr, ROWS, 1024, 1024, 0, 0);

        add_ln_kernel<<<ROWS, 256>>>(px, pt, g1 + bofs, be1 + bofs, px, ah, al, 1);

        gemm_tc<<<g_ff, 256, GEMM_SMEM_BYTES>>>(
            ah, al, w1t_h + wfofs, w1t_l + wfofs, b1 + b1ofs,
            nullptr, hh, hl, ROWS, 4096, 1024, 1, 1);

        gemm_tc<<<g_dd, 256, GEMM_SMEM_BYTES>>>(
            hh, hl, w2t_h + wfofs, w2t_l + wfofs, b2 + bofs,
            pt, nullptr, nullptr, ROWS, 1024, 4096, 0, 0);

        if (l == N_LAYERS - 1) {
            add_ln_kernel<<<ROWS, 256>>>(px, pt, g2 + bofs, be2 + bofs, out,
                                         ah, al, 0);
        } else {
            add_ln_kernel<<<ROWS, 256>>>(px, pt, g2 + bofs, be2 + bofs, px,
                                         ah, al, 1);
        }
    }
}

// round 9
// speedup vs baseline: 4.3726x; 1.0725x over previous
#include <cuda_runtime.h>
#include <cuda_bf16.h>
#include <math.h>
#include <stdint.h>

#define D_MODEL 1024
#define N_HEADS 16
#define D_K 64
#define D_FF 4096
#define N_LAYERS 6
#define BATCH 4
#define SEQ 1024
#define ROWS (BATCH * SEQ)   // 4096

// ---------------- scratch (device globals; no allocation allowed) ----------
__device__ float g_x[ROWS * D_MODEL];                 // residual stream (fp32)
__device__ float g_qkv[(size_t)ROWS * 3 * D_MODEL];   // fused QKV output
__device__ float g_t[ROWS * D_MODEL];                 // pre-LN gemm output
__device__ __nv_bfloat16 g_ah[(size_t)ROWS * D_MODEL];  // activation hi
__device__ __nv_bfloat16 g_al[(size_t)ROWS * D_MODEL];  // activation lo
__device__ __nv_bfloat16 g_hh[(size_t)ROWS * D_FF];     // ffn hidden hi
__device__ __nv_bfloat16 g_hl[(size_t)ROWS * D_FF];     // ffn hidden lo

// transposed + split weights: [N,K] K-major bf16, hi and lo parts
__device__ __nv_bfloat16 g_wqkvt_h[6u*3072*1024], g_wqkvt_l[6u*3072*1024];
__device__ __nv_bfloat16 g_wot_h[6u*1024*1024],  g_wot_l[6u*1024*1024];
__device__ __nv_bfloat16 g_w1t_h[6u*4096*1024],  g_w1t_l[6u*4096*1024];
__device__ __nv_bfloat16 g_w2t_h[6u*4096*1024],  g_w2t_l[6u*4096*1024];
__device__ float g_bqkv[6 * 3072];

// ---------------- PTX helpers ------------------------------------------------
__device__ __forceinline__ uint32_t smem_u32(const void* p) {
    uint32_t a;
    asm("{ .reg .u64 t; cvta.to.shared.u64 t, %1; cvt.u32.u64 %0, t; }"
        : "=r"(a) : "l"(p));
    return a;
}

__device__ __forceinline__ void cp16(uint32_t s, const void* g) {
    asm volatile("cp.async.cg.shared.global [%0], [%1], 16;"
                 :: "r"(s), "l"(g) : "memory");
}

__device__ __forceinline__ void ldsm4(uint32_t* r, uint32_t addr) {
    asm volatile("ldmatrix.sync.aligned.m8n8.x4.shared.b16 {%0,%1,%2,%3}, [%4];"
                 : "=r"(r[0]), "=r"(r[1]), "=r"(r[2]), "=r"(r[3]) : "r"(addr));
}

__device__ __forceinline__ void mma16816(float* c, const uint32_t* a,
                                         const uint32_t* b) {
    asm volatile(
        "mma.sync.aligned.m16n8k16.row.col.f32.bf16.bf16.f32 "
        "{%0,%1,%2,%3}, {%4,%5,%6,%7}, {%8,%9}, {%0,%1,%2,%3};"
        : "+f"(c[0]), "+f"(c[1]), "+f"(c[2]), "+f"(c[3])
        : "r"(a[0]), "r"(a[1]), "r"(a[2]), "r"(a[3]), "r"(b[0]), "r"(b[1]));
}

// split a float4 into bf16 hi/lo pairs, store 8B each
__device__ __forceinline__ void store_split4(__nv_bfloat16* H, __nv_bfloat16* L,
                                             size_t idx, float4 v) {
    __nv_bfloat162 h0 = __floats2bfloat162_rn(v.x, v.y);
    __nv_bfloat162 h1 = __floats2bfloat162_rn(v.z, v.w);
    float2 f0 = __bfloat1622float2(h0);
    float2 f1 = __bfloat1622float2(h1);
    __nv_bfloat162 l0 = __floats2bfloat162_rn(v.x - f0.x, v.y - f0.y);
    __nv_bfloat162 l1 = __floats2bfloat162_rn(v.z - f1.x, v.w - f1.y);
    uint2 hh, ll;
    hh.x = *reinterpret_cast<uint32_t*>(&h0);
    hh.y = *reinterpret_cast<uint32_t*>(&h1);
    ll.x = *reinterpret_cast<uint32_t*>(&l0);
    ll.y = *reinterpret_cast<uint32_t*>(&l1);
    *(uint2*)(H + idx) = hh;
    *(uint2*)(L + idx) = ll;
}

// ---------------- single-launch weight prep (transpose + bf16 split) --------
// One launch so the ncu capture window (-s 5 -c 1) lands on gemm_tc.
__global__ void prep_weights_kernel(
    const float* __restrict__ wq, const float* __restrict__ wk,
    const float* __restrict__ wv, const float* __restrict__ wo,
    const float* __restrict__ w1, const float* __restrict__ w2,
    __nv_bfloat16* __restrict__ qkvh, __nv_bfloat16* __restrict__ qkvl,
    __nv_bfloat16* __restrict__ woh,  __nv_bfloat16* __restrict__ wol,
    __nv_bfloat16* __restrict__ w1h,  __nv_bfloat16* __restrict__ w1l,
    __nv_bfloat16* __restrict__ w2h,  __nv_bfloat16* __restrict__ w2l) {
    __shared__ float t[32][33];
    const int tile = blockIdx.x;       // 0..12287
    const int layer = blockIdx.z;

    const float* W; __nv_bfloat16 *Th, *Tl;
    int K, N, row_off, tt; size_t lstride;
    if (tile < 1024)      { W = wq; Th = qkvh; Tl = qkvl; K = 1024; N = 1024;
                            row_off = 0;    lstride = (size_t)3072*1024; tt = tile; }
    else if (tile < 2048) { W = wk; Th = qkvh; Tl = qkvl; K = 1024; N = 1024;
                            row_off = 1024; lstride = (size_t)3072*1024; tt = tile - 1024; }
    else if (tile < 3072) { W = wv; Th = qkvh; Tl = qkvl; K = 1024; N = 1024;
                            row_off = 2048; lstride = (size_t)3072*1024; tt = tile - 2048; }
    else if (tile < 4096) { W = wo; Th = woh;  Tl = wol;  K = 1024; N = 1024;
                            row_off = 0;    lstride = (size_t)1024*1024; tt = tile - 3072; }
    else if (tile < 8192) { W = w1; Th = w1h;  Tl = w1l;  K = 1024; N = 4096;
                            row_off = 0;    lstride = (size_t)4096*1024; tt = tile - 4096; }
    else                  { W = w2; Th = w2h;  Tl = w2l;  K = 4096; N = 1024;
                            row_off = 0;    lstride = (size_t)4096*1024; tt = tile - 8192; }

    const int ntiles = N >> 5;
    const int n0 = (tt % ntiles) * 32, k0 = (tt / ntiles) * 32;
    const float* Wl = W + (size_t)layer * K * N;
    const int tx = threadIdx.x, ty = threadIdx.y;
#pragma unroll
    for (int i = ty; i < 32; i += 8)
        t[i][tx] = Wl[(size_t)(k0 + i) * N + n0 + tx];
    __syncthreads();
#pragma unroll
    for (int i = ty; i < 32; i += 8) {
        float v = t[tx][i];
        __nv_bfloat16 h = __float2bfloat16(v);
        float lo = v - __bfloat162float(h);
        size_t o = (size_t)layer * lstride +
                   (size_t)(row_off + n0 + i) * K + k0 + tx;
        Th[o] = h;
        Tl[o] = __float2bfloat16(lo);
    }
}

__global__ void concat_bias_kernel(const float* __restrict__ bq,
                                   const float* __restrict__ bk,
                                   const float* __restrict__ bv,
                                   float* __restrict__ dst) {
    int l = blockIdx.y;
    int i = blockIdx.x * 256 + threadIdx.x;   // 0..3071
    float v;
    if (i < 1024) v = bq[l * 1024 + i];
    else if (i < 2048) v = bk[l * 1024 + i - 1024];
    else v = bv[l * 1024 + i - 2048];
    dst[l * 3072 + i] = v;
}

// ---------------- mma.sync bf16 split-3 GEMM --------------------------------
// C[M,N] = A[M,K] @ B[N,K]^T + bias.
// 3-stage cp.async pipeline, ONE __syncthreads per BK=32 chunk, 2 CTAs/SM.
// SMEM tiles are 64B rows with XOR swizzle: chunk' = chunk ^ ((row>>1)&3)
// -> conflict-free ldsm (8 rows x 1 chunk hit 8 distinct bank groups).
#define S_AH 0
#define S_AL 8192
#define S_BH 16384
#define S_BL 24576
#define S_STG 32768
#define GEMM_SMEM_BYTES (3 * S_STG)   // 98304

__global__ __launch_bounds__(256, 2)
void gemm_tc(const __nv_bfloat16* __restrict__ Ah,
             const __nv_bfloat16* __restrict__ Al,
             const __nv_bfloat16* __restrict__ Bh,
             const __nv_bfloat16* __restrict__ Bl,
             const float* __restrict__ bias,
             float* __restrict__ C,
             __nv_bfloat16* __restrict__ Hout,
             __nv_bfloat16* __restrict__ Lout,
             int M, int N, int K, int relu, int outmode) {
    extern __shared__ char sm[];
    const uint32_t sb = smem_u32(sm);

    const int tid = threadIdx.x;
    const int l = tid & 31, w = tid >> 5;
    const int wm = w & 3, wn = w >> 2;
    const int m0 = blockIdx.y * 128, n0 = blockIdx.x * 128;

    // loader mapping: row = tid>>1 (0..127), chunks lkc, lkc+1 (16B each)
    const int lr = tid >> 1;
    const int lkc = (tid & 1) * 2;
    const uint32_t off0 = lr * 64 + ((lkc ^ ((lr >> 1) & 3)) << 4);
    const uint32_t off1 = off0 ^ 16;

    const __nv_bfloat16* agh = Ah + (size_t)(m0 + lr) * K + lkc * 8;
    const __nv_bfloat16* agl = Al + (size_t)(m0 + lr) * K + lkc * 8;
    const __nv_bfloat16* bgh = Bh + (size_t)(n0 + lr) * K + lkc * 8;
    const __nv_bfloat16* bgl = Bl + (size_t)(n0 + lr) * K + lkc * 8;

    auto issue = [&](int c) {
        const uint32_t o = sb + (c % 3) * S_STG;
        const size_t go = (size_t)c * 32;
        cp16(o + S_AH + off0, agh + go);
        cp16(o + S_AH + off1, agh + go + 8);
        cp16(o + S_AL + off0, agl + go);
        cp16(o + S_AL + off1, agl + go + 8);
        cp16(o + S_BH + off0, bgh + go);
        cp16(o + S_BH + off1, bgh + go + 8);
        cp16(o + S_BL + off0, bgl + go);
        cp16(o + S_BL + off1, bgl + go + 8);
        asm volatile("cp.async.commit_group;" ::: "memory");
    };

    float acc[2][8][4] = {};

    const int NCk = K >> 5;   // >= 32 always here
    issue(0);
    issue(1);

    // ldsm lane addressing (swizzled).
    // A: rows wm*32 + mi*16 + (l&15), chunk = 2*ks + (l>>4)
    const int ar_l = l & 15;
    const int a_ch = l >> 4;            // 0/1
    // B: rows wn*64 + nj*8 + ((l>>4)<<3) + (l&7), chunk = 2*ks + ((l>>3)&1)
    const int br_l = ((l >> 4) << 3) + (l & 7);
    const int b_ch = (l >> 3) & 1;

    for (int c = 0; c < NCk; c++) {
        if (c + 1 < NCk) {
            asm volatile("cp.async.wait_group 1;" ::: "memory");
        } else {
            asm volatile("cp.async.wait_group 0;" ::: "memory");
        }
        __syncthreads();
        if (c + 2 < NCk) issue(c + 2);

        const uint32_t o = sb + (c % 3) * S_STG;
#pragma unroll
        for (int ks = 0; ks < 2; ks++) {
            uint32_t ah[2][4], al_[2][4];
#pragma unroll
            for (int mi = 0; mi < 2; mi++) {
                const int ar = wm * 32 + mi * 16 + ar_l;
                const uint32_t aoff =
                    ar * 64 + (((2 * ks + a_ch) ^ ((ar >> 1) & 3)) << 4);
                ldsm4(ah[mi],  o + S_AH + aoff);
                ldsm4(al_[mi], o + S_AL + aoff);
            }
#pragma unroll
            for (int nj = 0; nj < 8; nj += 2) {
                const int br = wn * 64 + nj * 8 + br_l;
                const uint32_t boff =
                    br * 64 + (((2 * ks + b_ch) ^ ((br >> 1) & 3)) << 4);
                uint32_t bh2[4], bl2[4];
                ldsm4(bh2, o + S_BH + boff);
                ldsm4(bl2, o + S_BL + boff);
#pragma unroll
                for (int mi = 0; mi < 2; mi++) {
                    mma16816(acc[mi][nj],     ah[mi],  bh2);
                    mma16816(acc[mi][nj + 1], ah[mi],  bh2 + 2);
                    mma16816(acc[mi][nj],     ah[mi],  bl2);
                    mma16816(acc[mi][nj + 1], ah[mi],  bl2 + 2);
                    mma16816(acc[mi][nj],     al_[mi], bh2);
                    mma16816(acc[mi][nj + 1], al_[mi], bh2 + 2);
                }
            }
        }
    }

    const int gid = l >> 2, tig = l & 3;
#pragma unroll
    for (int mi = 0; mi < 2; mi++) {
        const int row0 = m0 + wm * 32 + mi * 16 + gid;
#pragma unroll
        for (int ni = 0; ni < 8; ni++) {
            const int col = n0 + wn * 64 + ni * 8 + tig * 2;
            float b0 = bias[col], b1 = bias[col + 1];
            float v0 = acc[mi][ni][0] + b0;
            float v1 = acc[mi][ni][1] + b1;
            float v2 = acc[mi][ni][2] + b0;
            float v3 = acc[mi][ni][3] + b1;
            if (relu) {
                v0 = fmaxf(v0, 0.0f); v1 = fmaxf(v1, 0.0f);
                v2 = fmaxf(v2, 0.0f); v3 = fmaxf(v3, 0.0f);
            }
            if (outmode == 0) {
                float2 p0 = {v0, v1}, p1 = {v2, v3};
                *(float2*)(C + (size_t)row0 * N + col) = p0;
                *(float2*)(C + (size_t)(row0 + 8) * N + col) = p1;
            } else {
                __nv_bfloat162 h0 = __floats2bfloat162_rn(v0, v1);
                float2 f0 = __bfloat1622float2(h0);
                __nv_bfloat162 l0 = __floats2bfloat162_rn(v0 - f0.x, v1 - f0.y);
                __nv_bfloat162 h1 = __floats2bfloat162_rn(v2, v3);
                float2 f1 = __bfloat1622float2(h1);
                __nv_bfloat162 l1 = __floats2bfloat162_rn(v2 - f1.x, v3 - f1.y);
                *(__nv_bfloat162*)(Hout + (size_t)row0 * N + col) = h0;
                *(__nv_bfloat162*)(Lout + (size_t)row0 * N + col) = l0;
                *(__nv_bfloat162*)(Hout + (size_t)(row0 + 8) * N + col) = h1;
                *(__nv_bfloat162*)(Lout + (size_t)(row0 + 8) * N + col) = l1;
            }
        }
    }
}

// ---------------- embedding + PE, fused bf16 split ---------------------------
__global__ __launch_bounds__(256)
void embed_kernel(const int* __restrict__ src,
                  const float* __restrict__ emb,
                  const float* __restrict__ pe,
                  float* __restrict__ x,
                  __nv_bfloat16* __restrict__ H,
                  __nv_bfloat16* __restrict__ L) {
    int row = blockIdx.x;
    int s = row & (SEQ - 1);
    int tok = src[row];
    int c = threadIdx.x * 4;
    const float* erow = emb + (size_t)tok * D_MODEL;
    const float* prow = pe + (size_t)s * D_MODEL;
    float4 e = *(const float4*)(erow + c);
    float4 p = *(const float4*)(prow + c);
    float4 v;
    v.x = e.x * 32.0f + p.x; v.y = e.y * 32.0f + p.y;
    v.z = e.z * 32.0f + p.z; v.w = e.w * 32.0f + p.w;
    size_t idx = (size_t)row * D_MODEL + c;
    *(float4*)(x + idx) = v;
    store_split4(H, L, idx, v);
}

// ---------------- flash-style tiled attention --------------------------------
#define ATT_STRIDE 68
#define QKV_STRIDE 3072
#define ATT_SMEM_BYTES ((4 * 64 * ATT_STRIDE) * 4 + 256)

__global__ __launch_bounds__(256, 2)
void attn_tile_kernel(const float* __restrict__ QKV,
                      const int* __restrict__ mask,
                      __nv_bfloat16* __restrict__ Hh,
                      __nv_bfloat16* __restrict__ Ll) {
    extern __shared__ float shm[];
    float* Qs = shm;                            // [64][68]
    float* Ks = shm + 64 * ATT_STRIDE;
    float* Ps = shm + 2 * 64 * ATT_STRIDE;
    float* Vs = shm + 3 * 64 * ATT_STRIDE;
    int*   ms = (int*)(shm + 4 * 64 * ATT_STRIDE);

    const int tid = threadIdx.x;
    const int g = tid & 7;
    const int qp = tid >> 3;                    // 0..31
    const int qt = blockIdx.x, h = blockIdx.y, b = blockIdx.z;

    const int lrow = tid >> 2, lcol = (tid & 3) * 16;
    const float* Qg = QKV + ((size_t)(b * SEQ + qt * 64)) * QKV_STRIDE + h * D_K;
    const float* Kg = QKV + ((size_t)(b * SEQ)) * QKV_STRIDE + 1024 + h * D_K;
    const float* Vg = QKV + ((size_t)(b * SEQ)) * QKV_STRIDE + 2048 + h * D_K;

#pragma unroll
    for (int c = 0; c < 16; c += 4)
        *(float4*)&Qs[lrow * ATT_STRIDE + lcol + c] =
            *(const float4*)(Qg + (size_t)lrow * QKV_STRIDE + lcol + c);

    float m0 = -1e30f, m1 = -1e30f, l0 = 0.0f, l1 = 0.0f;
    float O0[8] = {0}, O1[8] = {0};

    for (int kt = 0; kt < SEQ / 64; kt++) {
        __syncthreads();
#pragma unroll
        for (int c = 0; c < 16; c += 4) {
            *(float4*)&Ks[lrow * ATT_STRIDE + lcol + c] =
                *(const float4*)(Kg + (size_t)(kt * 64 + lrow) * QKV_STRIDE + lcol + c);
            *(float4*)&Vs[lrow * ATT_STRIDE + lcol + c] =
                *(const float4*)(Vg + (size_t)(kt * 64 + lrow) * QKV_STRIDE + lcol + c);
        }
        if (tid < 64) ms[tid] = mask[b * SEQ + kt * 64 + tid];
        __syncthreads();

        float s0[8] = {0}, s1[8] = {0};
#pragma unroll
        for (int d = 0; d < 64; d += 4) {
            float4 qa = *(const float4*)&Qs[qp * ATT_STRIDE + d];
            float4 qb = *(const float4*)&Qs[(qp + 32) * ATT_STRIDE + d];
#pragma unroll
            for (int jj = 0; jj < 8; jj++) {
                float4 kv = *(const float4*)&Ks[(g + 8 * jj) * ATT_STRIDE + d];
                s0[jj] = fmaf(qa.x, kv.x, fmaf(qa.y, kv.y,
                          fmaf(qa.z, kv.z, fmaf(qa.w, kv.w, s0[jj]))));
                s1[jj] = fmaf(qb.x, kv.x, fmaf(qb.y, kv.y,
                          fmaf(qb.z, kv.z, fmaf(qb.w, kv.w, s1[jj]))));
            }
        }

        float tm0 = -1e30f, tm1 = -1e30f;
#pragma unroll
        for (int jj = 0; jj < 8; jj++) {
            int msk = ms[g + 8 * jj];
            float a0 = msk ? s0[jj] * 0.125f : -1e9f;
            float a1 = msk ? s1[jj] * 0.125f : -1e9f;
            s0[jj] = a0; s1[jj] = a1;
            tm0 = fmaxf(tm0, a0); tm1 = fmaxf(tm1, a1);
        }
#pragma unroll
        for (int o = 1; o < 8; o <<= 1) {
            tm0 = fmaxf(tm0, __shfl_xor_sync(0xffffffffu, tm0, o));
            tm1 = fmaxf(tm1, __shfl_xor_sync(0xffffffffu, tm1, o));
        }
        float mn0 = fmaxf(m0, tm0), mn1 = fmaxf(m1, tm1);
        float sc0 = __expf(m0 - mn0), sc1 = __expf(m1 - mn1);
        m0 = mn0; m1 = mn1;

        float ps0 = 0.0f, ps1 = 0.0f;
#pragma unroll
        for (int jj = 0; jj < 8; jj++) {
            float p0 = __expf(s0[jj] - mn0);
            float p1 = __expf(s1[jj] - mn1);
            ps0 += p0; ps1 += p1;
            Ps[qp * ATT_STRIDE + g + 8 * jj] = p0;
            Ps[(qp + 32) * ATT_STRIDE + g + 8 * jj] = p1;
        }
#pragma unroll
        for (int o = 1; o < 8; o <<= 1) {
            ps0 += __shfl_xor_sync(0xffffffffu, ps0, o);
            ps1 += __shfl_xor_sync(0xffffffffu, ps1, o);
        }
        l0 = l0 * sc0 + ps0;
        l1 = l1 * sc1 + ps1;
#pragma unroll
        for (int c = 0; c < 8; c++) { O0[c] *= sc0; O1[c] *= sc1; }
        __syncwarp();

#pragma unroll 4
        for (int j = 0; j < 64; j++) {
            float p0 = Ps[qp * ATT_STRIDE + j];
            float p1 = Ps[(qp + 32) * ATT_STRIDE + j];
            float4 va = *(const float4*)&Vs[j * ATT_STRIDE + 4 * g];
            float4 vb = *(const float4*)&Vs[j * ATT_STRIDE + 32 + 4 * g];
            O0[0] = fmaf(p0, va.x, O0[0]); O0[1] = fmaf(p0, va.y, O0[1]);
            O0[2] = fmaf(p0, va.z, O0[2]); O0[3] = fmaf(p0, va.w, O0[3]);
            O0[4] = fmaf(p0, vb.x, O0[4]); O0[5] = fmaf(p0, vb.y, O0[5]);
            O0[6] = fmaf(p0, vb.z, O0[6]); O0[7] = fmaf(p0, vb.w, O0[7]);
            O1[0] = fmaf(p1, va.x, O1[0]); O1[1] = fmaf(p1, va.y, O1[1]);
            O1[2] = fmaf(p1, va.z, O1[2]); O1[3] = fmaf(p1, va.w, O1[3]);
            O1[4] = fmaf(p1, vb.x, O1[4]); O1[5] = fmaf(p1, vb.y, O1[5]);
            O1[6] = fmaf(p1, vb.z, O1[6]); O1[7] = fmaf(p1, vb.w, O1[7]);
        }
    }

    const float inv0 = 1.0f / l0, inv1 = 1.0f / l1;
    size_t r0 = (size_t)(b * SEQ + qt * 64 + qp) * D_MODEL + h * D_K;
    size_t r1 = (size_t)(b * SEQ + qt * 64 + qp + 32) * D_MODEL + h * D_K;
    float4 w;
    w.x = O0[0] * inv0; w.y = O0[1] * inv0; w.z = O0[2] * inv0; w.w = O0[3] * inv0;
    store_split4(Hh, Ll, r0 + 4 * g, w);
    w.x = O0[4] * inv0; w.y = O0[5] * inv0; w.z = O0[6] * inv0; w.w = O0[7] * inv0;
    store_split4(Hh, Ll, r0 + 32 + 4 * g, w);
    w.x = O1[0] * inv1; w.y = O1[1] * inv1; w.z = O1[2] * inv1; w.w = O1[3] * inv1;
    store_split4(Hh, Ll, r1 + 4 * g, w);
    w.x = O1[4] * inv1; w.y = O1[5] * inv1; w.z = O1[6] * inv1; w.w = O1[7] * inv1;
    store_split4(Hh, Ll, r1 + 32 + 4 * g, w);
}

// ---------------- fused residual add + LayerNorm + optional bf16 split ------
__global__ __launch_bounds__(256)
void add_ln_kernel(const float* __restrict__ x,
                   const float* __restrict__ r,
                   const float* __restrict__ g,
                   const float* __restrict__ bta,
                   float* __restrict__ y,
                   __nv_bfloat16* __restrict__ H,
                   __nv_bfloat16* __restrict__ L,
                   int write_split) {
    const int row = blockIdx.x;
    const int tid = threadIdx.x;
    const int c = tid * 4;
    const size_t idx = (size_t)row * D_MODEL + c;

    float4 xv = *(const float4*)(x + idx);
    float4 rv = *(const float4*)(r + idx);
    float4 v;
    v.x = xv.x + rv.x; v.y = xv.y + rv.y;
    v.z = xv.z + rv.z; v.w = xv.w + rv.w;

    float s = v.x + v.y + v.z + v.w;
    float ss = fmaf(v.x, v.x, fmaf(v.y, v.y, fmaf(v.z, v.z, v.w * v.w)));

    __shared__ float rs[256], rss[256];
    rs[tid] = s; rss[tid] = ss;
    __syncthreads();
    for (int off = 128; off > 0; off >>= 1) {
        if (tid < off) { rs[tid] += rs[tid + off]; rss[tid] += rss[tid + off]; }
        __syncthreads();
    }
    float mean = rs[0] * (1.0f / D_MODEL);
    float var = rss[0] * (1.0f / D_MODEL) - mean * mean;
    float inv = rsqrtf(var + 1e-5f);

    float4 gg = *(const float4*)(g + c);
    float4 bb = *(const float4*)(bta + c);
    float4 o;
    o.x = (v.x - mean) * inv * gg.x + bb.x;
    o.y = (v.y - mean) * inv * gg.y + bb.y;
    o.z = (v.z - mean) * inv * gg.z + bb.z;
    o.w = (v.w - mean) * inv * gg.w + bb.w;
    *(float4*)(y + idx) = o;
    if (write_split) store_split4(H, L, idx, o);
}

// ---------------- host orchestration ---------------------------------------
extern "C" void kernel_launch(void* const* d_in, const int* in_sizes, int n_in,
                              void* d_out, int out_size) {
    const int*   src  = (const int*)d_in[0];
    const int*   mask = (const int*)d_in[1];
    const float* emb  = (const float*)d_in[2];
    const float* pe   = (const float*)d_in[3];
    const float* wq = (const float*)d_in[4];
    const float* bq = (const float*)d_in[5];
    const float* wk = (const float*)d_in[6];
    const float* bk = (const float*)d_in[7];
    const float* wv = (const float*)d_in[8];
    const float* bv = (const float*)d_in[9];
    const float* wo = (const float*)d_in[10];
    const float* bo = (const float*)d_in[11];
    const float* w1 = (const float*)d_in[12];
    const float* b1 = (const float*)d_in[13];
    const float* w2 = (const float*)d_in[14];
    const float* b2 = (const float*)d_in[15];
    const float* g1  = (const float*)d_in[16];
    const float* be1 = (const float*)d_in[17];
    const float* g2  = (const float*)d_in[18];
    const float* be2 = (const float*)d_in[19];
    float* out = (float*)d_out;

    float *px, *pqkv, *pt, *pbqkv;
    cudaGetSymbolAddress((void**)&px, g_x);
    cudaGetSymbolAddress((void**)&pqkv, g_qkv);
    cudaGetSymbolAddress((void**)&pt, g_t);
    cudaGetSymbolAddress((void**)&pbqkv, g_bqkv);

    __nv_bfloat16 *ah, *al, *hh, *hl;
    cudaGetSymbolAddress((void**)&ah, g_ah);
    cudaGetSymbolAddress((void**)&al, g_al);
    cudaGetSymbolAddress((void**)&hh, g_hh);
    cudaGetSymbolAddress((void**)&hl, g_hl);

    __nv_bfloat16 *wqkvt_h, *wqkvt_l, *wot_h, *wot_l;
    __nv_bfloat16 *w1t_h, *w1t_l, *w2t_h, *w2t_l;
    cudaGetSymbolAddress((void**)&wqkvt_h, g_wqkvt_h);
    cudaGetSymbolAddress((void**)&wqkvt_l, g_wqkvt_l);
    cudaGetSymbolAddress((void**)&wot_h, g_wot_h);
    cudaGetSymbolAddress((void**)&wot_l, g_wot_l);
    cudaGetSymbolAddress((void**)&w1t_h, g_w1t_h);
    cudaGetSymbolAddress((void**)&w1t_l, g_w1t_l);
    cudaGetSymbolAddress((void**)&w2t_h, g_w2t_h);
    cudaGetSymbolAddress((void**)&w2t_l, g_w2t_l);

    static int attr_set = 0;
    if (!attr_set) {
        cudaFuncSetAttribute(gemm_tc, cudaFuncAttributeMaxDynamicSharedMemorySize,
                             GEMM_SMEM_BYTES);
        cudaFuncSetAttribute(attn_tile_kernel,
                             cudaFuncAttributeMaxDynamicSharedMemorySize,
                             ATT_SMEM_BYTES);
        attr_set = 1;
    }

    // ---- weight prep: ONE launch ----
    prep_weights_kernel<<<dim3(12288, 1, 6), dim3(32, 8)>>>(
        wq, wk, wv, wo, w1, w2,
        wqkvt_h, wqkvt_l, wot_h, wot_l, w1t_h, w1t_l, w2t_h, w2t_l);
    concat_bias_kernel<<<dim3(12, 6), 256>>>(bq, bk, bv, pbqkv);

    embed_kernel<<<ROWS, 256>>>(src, emb, pe, px, ah, al);

    dim3 g_qkv_grid(3072 / 128, ROWS / 128);   // (24, 32)
    dim3 g_dd(D_MODEL / 128, ROWS / 128);      // (8, 32)
    dim3 g_ff(D_FF / 128,    ROWS / 128);      // (32, 32)
    dim3 attn_grid(SEQ / 64, N_HEADS, BATCH);

    for (int l = 0; l < N_LAYERS; l++) {
        size_t woqkv = (size_t)l * 3072 * 1024;
        size_t wofs  = (size_t)l * 1024 * 1024;
        size_t bofs  = (size_t)l * D_MODEL;
        size_t wfofs = (size_t)l * 4096 * 1024;
        size_t b1ofs = (size_t)l * D_FF;

        gemm_tc<<<g_qkv_grid, 256, GEMM_SMEM_BYTES>>>(
            ah, al, wqkvt_h + woqkv, wqkvt_l + woqkv, pbqkv + l * 3072,
            pqkv, nullptr, nullptr, ROWS, 3072, 1024, 0, 0);

        attn_tile_kernel<<<attn_grid, 256, ATT_SMEM_BYTES>>>(pqkv, mask, ah, al);

        gemm_tc<<<g_dd, 256, GEMM_SMEM_BYTES>>>(
            ah, al, wot_h + wofs, wot_l + wofs, bo + bofs,
            pt, nullptr, nullptr, ROWS, 1024, 1024, 0, 0);

        add_ln_kernel<<<ROWS, 256>>>(px, pt, g1 + bofs, be1 + bofs, px, ah, al, 1);

        gemm_tc<<<g_ff, 256, GEMM_SMEM_BYTES>>>(
            ah, al, w1t_h + wfofs, w1t_l + wfofs, b1 + b1ofs,
            nullptr, hh, hl, ROWS, 4096, 1024, 1, 1);

        gemm_tc<<<g_dd, 256, GEMM_SMEM_BYTES>>>(
            hh, hl, w2t_h + wfofs, w2t_l + wfofs, b2 + bofs,
            pt, nullptr, nullptr, ROWS, 1024, 4096, 0, 0);

        if (l == N_LAYERS - 1) {
            add_ln_kernel<<<ROWS, 256>>>(px, pt, g2 + bofs, be2 + bofs, out,
                                         ah, al, 0);
        } else {
            add_ln_kernel<<<ROWS, 256>>>(px, pt, g2 + bofs, be2 + bofs, px,
                                         ah, al, 1);
        }
    }
}